// round 14
// baseline (speedup 1.0000x reference)
#include <cuda_runtime.h>
#include <cuda_bf16.h>
#include <cstdint>

// ---------------------------------------------------------------------------
// Focus-DETR encoder — round 14: taller GEMM tiles (128x128 gemm2, 64-row
// gemm_ln) to halve weight L2 traffic; attn exp interleaved with PV mma.
// Numerics identical to round 13 (bf16 single-term, no-rescale softmax).
// ---------------------------------------------------------------------------

#define L_LAYERS 6
#define Bn 4
#define NN 23890
#define Kn 1024
#define Dn 256
#define Hn 8
#define HDn 32
#define FFNn 1024
#define NCLSn 15

#define ROWS (Bn * Kn)          // 4096
#define RD   (ROWS * Dn)        // 1048576 elements

// ---------------- scratch carving ----------------
constexpr size_t SZ_F  = (size_t)RD * 4;
constexpr size_t SZ_B  = (size_t)RD * 2;
constexpr size_t SZ_H  = (size_t)ROWS * FFNn * 2;
constexpr size_t SZ_WD = (size_t)L_LAYERS * Dn * Dn * 2;
constexpr size_t SZ_W1 = (size_t)L_LAYERS * Dn * FFNn * 2;

constexpr size_t OF_TGT = 0;
constexpr size_t OF_XB  = OF_TGT + SZ_F;
constexpr size_t OF_QKH = OF_XB  + SZ_F;
constexpr size_t OF_TGH = OF_QKH + SZ_B;
constexpr size_t OF_QH  = OF_TGH + SZ_B;
constexpr size_t OF_KH  = OF_QH  + SZ_B;
constexpr size_t OF_VH  = OF_KH  + SZ_B;
constexpr size_t OF_ATH = OF_VH  + SZ_B;
constexpr size_t OF_XH  = OF_ATH + SZ_B;
constexpr size_t OF_HH  = OF_XH  + SZ_B;
constexpr size_t OF_WQH = OF_HH  + SZ_H;
constexpr size_t OF_WKH = OF_WQH + SZ_WD;
constexpr size_t OF_WVH = OF_WKH + SZ_WD;
constexpr size_t OF_WOH = OF_WVH + SZ_WD;
constexpr size_t OF_W1H = OF_WOH + SZ_WD;
constexpr size_t OF_W2H = OF_W1H + SZ_W1;
constexpr size_t G_TOTAL = OF_W2H + SZ_W1;

__device__ __align__(1024) unsigned char g_mem[G_TOTAL];

#define BETA 0.2550165213f      // log2(e)/sqrt(32), folded into Q

// ============================ PTX helpers ==================================

__device__ __forceinline__ uint32_t smem_u32(const void* p) {
    uint32_t a;
    asm("{ .reg .u64 t; cvta.to.shared.u64 t, %1; cvt.u32.u64 %0, t; }"
        : "=r"(a) : "l"(p));
    return a;
}

#define CP16(sa, ga)                                                            \
    asm volatile("cp.async.ca.shared.global [%0], [%1], 16;"                    \
                 :: "r"(sa), "l"(__cvta_generic_to_global(ga)))
#define CP_COMMIT() asm volatile("cp.async.commit_group;" ::: "memory")
#define CP_WAIT0()  asm volatile("cp.async.wait_group 0;" ::: "memory")
#define CP_WAIT1()  asm volatile("cp.async.wait_group 1;" ::: "memory")

#define LDSM4(r, addr)                                                          \
    asm volatile("ldmatrix.sync.aligned.m8n8.x4.shared.b16 {%0,%1,%2,%3}, [%4];"\
        : "=r"((r)[0]), "=r"((r)[1]), "=r"((r)[2]), "=r"((r)[3]) : "r"(addr))

#define MMA_BF16(d, a, b0, b1)                                                  \
    asm volatile("mma.sync.aligned.m16n8k16.row.col.f32.bf16.bf16.f32 "         \
        "{%0,%1,%2,%3}, {%4,%5,%6,%7}, {%8,%9}, {%0,%1,%2,%3};"                 \
        : "+f"((d)[0]), "+f"((d)[1]), "+f"((d)[2]), "+f"((d)[3])                \
        : "r"((a)[0]), "r"((a)[1]), "r"((a)[2]), "r"((a)[3]), "r"(b0), "r"(b1))

__device__ __forceinline__ uint32_t bf2_u32(__nv_bfloat16 a, __nv_bfloat16 b) {
    union { __nv_bfloat162 v; uint32_t u; } cvt;
    cvt.v = __halves2bfloat162(a, b);
    return cvt.u;
}

__device__ __forceinline__ uint32_t pack2(float v0, float v1) {
    return bf2_u32(__float2bfloat16(v0), __float2bfloat16(v1));
}

__device__ __forceinline__ float ex2(float x) {
    float r;
    asm("ex2.approx.ftz.f32 %0, %1;" : "=f"(r) : "f"(x));
    return r;
}

// ================== weight prep: all weights (hi only) =====================
struct WprepP {
    const float* src[6];
    __nv_bfloat16* dh[6];
};

__global__ __launch_bounds__(256) void wprep_all(WprepP p)
{
    __shared__ float tile[32][33];
    int bid = blockIdx.x;
    int g, layer, kt, nt, Kd, N;
    if (bid < 1536) {
        g = bid / 384; int r = bid % 384;
        layer = r >> 6; int t = r & 63;
        kt = t >> 3; nt = t & 7; Kd = 256; N = 256;
    } else if (bid < 3072) {
        g = 4; int r = bid - 1536;
        layer = r >> 8; int t = r & 255;
        kt = t >> 5; nt = t & 31; Kd = 256; N = 1024;
    } else {
        g = 5; int r = bid - 3072;
        layer = r >> 8; int t = r & 255;
        kt = t >> 3; nt = t & 7; Kd = 1024; N = 256;
    }
    const int k0 = kt << 5, n0 = nt << 5;
    const int tx = threadIdx.x & 31, ty = threadIdx.x >> 5;

    const float* Wp = p.src[g] + (size_t)layer * Kd * N;
#pragma unroll
    for (int r = ty; r < 32; r += 8)
        tile[r][tx] = Wp[(size_t)(k0 + r) * N + n0 + tx];
    __syncthreads();

    __nv_bfloat16* Hp = p.dh[g] + ((size_t)layer * N + n0) * Kd + k0;
#pragma unroll
    for (int r = ty; r < 32; r += 8)
        Hp[(size_t)r * Kd + tx] = __float2bfloat16(tile[tx][r]);
}

// ===================== bf16 GEMM: 256 thr, tile 128x128 ====================
struct GemmP {
    const __nv_bfloat16 *Ah[3], *Wh[3];
    const float* bias[3];
    __nv_bfloat16 *Ch[3];
};

#define G2_AH 0
#define G2_BH 10240
#define G2_BUF 20480
#define G2_SMEM (2 * G2_BUF)

__global__ __launch_bounds__(256) void gemm2(GemmP p, int Ncols, int Kd, int mode)
{
    extern __shared__ __align__(16) char smem[];
    const uint32_t sb = smem_u32(smem);

    const int z    = blockIdx.z;
    const __nv_bfloat16* Ah = p.Ah[z];
    const __nv_bfloat16* Wh = p.Wh[z];

    const int tid  = threadIdx.x;
    const int lane = tid & 31;
    const int wid  = tid >> 5;
    const int wm   = wid & 1;           // 2 M halves of 64
    const int wn   = wid >> 1;          // 4 N quarters of 32
    const int bm   = blockIdx.y << 7;
    const int bn   = blockIdx.x << 7;

    float acc[4][4][4];
#pragma unroll
    for (int i = 0; i < 4; i++)
#pragma unroll
        for (int j = 0; j < 4; j++)
#pragma unroll
            for (int q = 0; q < 4; q++) acc[i][j][q] = 0.0f;

    const int a_r = wm * 64 + (lane & 15);
    const int a_c = (lane >> 4) << 3;
    const int b_r = wn * 32 + (lane & 7) + ((lane >> 4) << 3);
    const int b_c = ((lane >> 3) & 1) << 3;

    const int nc = Kd >> 5;

    auto issue = [&](int c, int buf) {
        const uint32_t sa = sb + buf * G2_BUF;
        const size_t kb = (size_t)(c << 5) * 2;
#pragma unroll
        for (int i = 0; i < 2; i++) {           // A: 128 rows x 4 segs = 512
            int s = tid + (i << 8);
            int row = s >> 2, seg = s & 3;
            size_t go = ((size_t)(bm + row) * Kd) * 2 + kb + seg * 16;
            uint32_t so = sa + row * 80 + seg * 16;
            CP16(so + G2_AH, (const char*)Ah + go);
        }
#pragma unroll
        for (int i = 0; i < 2; i++) {           // B: 128 rows x 4 segs = 512
            int s = tid + (i << 8);
            int row = s >> 2, seg = s & 3;
            size_t go = ((size_t)(bn + row) * Kd) * 2 + kb + seg * 16;
            uint32_t so = sa + row * 80 + seg * 16;
            CP16(so + G2_BH, (const char*)Wh + go);
        }
        CP_COMMIT();
    };

    issue(0, 0);

    for (int c = 0; c < nc; c++) {
        const int buf = c & 1;
        if (c + 1 < nc) { issue(c + 1, buf ^ 1); CP_WAIT1(); }
        else           { CP_WAIT0(); }
        __syncthreads();

        const uint32_t sa = sb + buf * G2_BUF;
#pragma unroll
        for (int ks = 0; ks < 2; ks++) {
            uint32_t ah[4][4];
#pragma unroll
            for (int mb = 0; mb < 4; mb++) {
                uint32_t ao = sa + (uint32_t)(a_r + mb * 16) * 80 + (ks * 16 + a_c) * 2;
                LDSM4(ah[mb], ao + G2_AH);
            }
            uint32_t bh[2][4];
#pragma unroll
            for (int np = 0; np < 2; np++) {
                uint32_t bo = sa + (uint32_t)(b_r + np * 16) * 80 + (ks * 16 + b_c) * 2;
                LDSM4(bh[np], bo + G2_BH);
            }
#pragma unroll
            for (int mb = 0; mb < 4; mb++)
#pragma unroll
                for (int nb = 0; nb < 4; nb++) {
                    const int np = nb >> 1, sl = (nb & 1) << 1;
                    MMA_BF16(acc[mb][nb], ah[mb], bh[np][sl], bh[np][sl + 1]);
                }
        }
        __syncthreads();
    }

    const float* bias = p.bias[z];
    const int r0 = bm + wm * 64 + (lane >> 2);
    const int c0 = bn + wn * 32 + ((lane & 3) << 1);

    if (mode == 2) {   // FFN1: relu + bf16 out
        __nv_bfloat16* Ch = p.Ch[z];
#pragma unroll
        for (int mb = 0; mb < 4; mb++)
#pragma unroll
            for (int nb = 0; nb < 4; nb++) {
                int rr = r0 + mb * 16, cc = c0 + nb * 8;
                float bb0 = bias[cc], bb1 = bias[cc + 1];
#pragma unroll
                for (int hrow = 0; hrow < 2; hrow++) {
                    int r = rr + hrow * 8;
                    float v0 = fmaxf(acc[mb][nb][2 * hrow]     + bb0, 0.0f);
                    float v1 = fmaxf(acc[mb][nb][2 * hrow + 1] + bb1, 0.0f);
                    *(uint32_t*)(Ch + (size_t)r * Ncols + cc) = pack2(v0, v1);
                }
            }
    } else {           // mode 3: attention QKV layout (Q pre-scaled by BETA)
        __nv_bfloat16* Ch = p.Ch[z];
        const float qscale = (z == 0) ? BETA : 1.0f;
#pragma unroll
        for (int mb = 0; mb < 4; mb++)
#pragma unroll
            for (int nb = 0; nb < 4; nb++) {
                int rr = r0 + mb * 16, cc = c0 + nb * 8;
                float bb0 = bias[cc], bb1 = bias[cc + 1];
                int bh = ((rr >> 10) << 3) + (cc >> 5);
                int d  = cc & 31;
#pragma unroll
                for (int hrow = 0; hrow < 2; hrow++) {
                    int r = rr + hrow * 8;
                    int q = r & 1023;
                    float v0 = (acc[mb][nb][2 * hrow]     + bb0) * qscale;
                    float v1 = (acc[mb][nb][2 * hrow + 1] + bb1) * qscale;
                    if (z < 2) {
                        size_t a = ((size_t)bh * 1024 + q) * 32 + d;
                        *(uint32_t*)(Ch + a) = pack2(v0, v1);
                    } else {
                        size_t a = ((size_t)bh * 32 + d) * 1024 + q;
                        Ch[a] = __float2bfloat16(v0);
                        Ch[a + 1024] = __float2bfloat16(v1);
                    }
                }
            }
    }
}

// ================= GEMM + LayerNorm fused: 64-row tiles ====================
#define GL_AH 0
#define GL_BH 5120
#define GL_BUF 25600
#define GL_RED   51200          // 64 rows x 8 warps x float2 = 4096
#define GL_BIAS  55296
#define GL_GAM   56320
#define GL_BET   57344
#define GL_SMEM  58368

__global__ __launch_bounds__(256) void gemm_ln(
    const __nv_bfloat16* __restrict__ Ah,
    const __nv_bfloat16* __restrict__ Wh,
    const float* __restrict__ bias, const float* __restrict__ gam,
    const float* __restrict__ bet, const float* __restrict__ res,
    float* __restrict__ Xout, __nv_bfloat16* __restrict__ Xh,
    float* __restrict__ out, const int* __restrict__ il,
    const int* __restrict__ fnum,
    int Kd, int mode)
{
    extern __shared__ __align__(16) char smem[];
    const uint32_t sb = smem_u32(smem);

    const int tid  = threadIdx.x;
    const int lane = tid & 31;
    const int w    = tid >> 5;          // warp owns cols [32w, 32w+32)
    const int bm   = blockIdx.y << 6;   // 64 rows per CTA

    ((float*)(smem + GL_BIAS))[tid] = bias[tid];
    ((float*)(smem + GL_GAM))[tid]  = gam[tid];
    ((float*)(smem + GL_BET))[tid]  = bet[tid];

    float acc[4][4][4];
#pragma unroll
    for (int i = 0; i < 4; i++)
#pragma unroll
        for (int j = 0; j < 4; j++)
#pragma unroll
            for (int q = 0; q < 4; q++) acc[i][j][q] = 0.0f;

    const int a_r = lane & 15;
    const int a_c = (lane >> 4) << 3;
    const int b_rr = (lane & 7) + ((lane >> 4) << 3);
    const int b_cc = ((lane >> 3) & 1) << 3;

    const int nc = Kd >> 5;

    auto issue = [&](int c, int buf) {
        const uint32_t sa = sb + buf * GL_BUF;
        const size_t kb = (size_t)(c << 5) * 2;
        {                                       // A: 64 rows x 4 segs = 256
            int row = tid >> 2, seg = tid & 3;
            size_t go = ((size_t)(bm + row) * Kd) * 2 + kb + seg * 16;
            uint32_t so = sa + row * 80 + seg * 16;
            CP16(so + GL_AH, (const char*)Ah + go);
        }
#pragma unroll
        for (int i = 0; i < 4; i++) {           // B: 256 rows x 4 segs = 1024
            int s = tid + (i << 8);
            int row = s >> 2, seg = s & 3;
            size_t go = ((size_t)row * Kd) * 2 + kb + seg * 16;
            uint32_t so = sa + row * 80 + seg * 16;
            CP16(so + GL_BH, (const char*)Wh + go);
        }
        CP_COMMIT();
    };

    issue(0, 0);

    for (int c = 0; c < nc; c++) {
        const int buf = c & 1;
        if (c + 1 < nc) { issue(c + 1, buf ^ 1); CP_WAIT1(); }
        else           { CP_WAIT0(); }
        __syncthreads();

        const uint32_t sa = sb + buf * GL_BUF;
#pragma unroll
        for (int ks = 0; ks < 2; ks++) {
            uint32_t ah[4][4];
#pragma unroll
            for (int mb = 0; mb < 4; mb++) {
                uint32_t ao = sa + (uint32_t)(mb * 16 + a_r) * 80 + (ks * 16 + a_c) * 2;
                LDSM4(ah[mb], ao + GL_AH);
            }
            uint32_t bh[2][4];
#pragma unroll
            for (int np = 0; np < 2; np++) {
                uint32_t bo = sa + (uint32_t)(w * 32 + np * 16 + b_rr) * 80
                            + (ks * 16 + b_cc) * 2;
                LDSM4(bh[np], bo + GL_BH);
            }
#pragma unroll
            for (int mb = 0; mb < 4; mb++)
#pragma unroll
                for (int nb = 0; nb < 4; nb++) {
                    const int np = nb >> 1, sl = (nb & 1) << 1;
                    MMA_BF16(acc[mb][nb], ah[mb], bh[np][sl], bh[np][sl + 1]);
                }
        }
        __syncthreads();
    }

    const float* bias_s = (const float*)(smem + GL_BIAS);
    float2* red = (float2*)(smem + GL_RED);

#pragma unroll
    for (int mb = 0; mb < 4; mb++) {
        float sA = 0.f, qA = 0.f, sB = 0.f, qB = 0.f;
#pragma unroll
        for (int nb = 0; nb < 4; nb++) {
            int cc = w * 32 + nb * 8 + ((lane & 3) << 1);
            int rA = bm + mb * 16 + (lane >> 2);
            int rB = rA + 8;
            float2 resA = *(const float2*)(res + (size_t)rA * Dn + cc);
            float2 resB = *(const float2*)(res + (size_t)rB * Dn + cc);
            float bb0 = bias_s[cc], bb1 = bias_s[cc + 1];
            float v;
            v = acc[mb][nb][0] + bb0 + resA.x; acc[mb][nb][0] = v; sA += v; qA += v * v;
            v = acc[mb][nb][1] + bb1 + resA.y; acc[mb][nb][1] = v; sA += v; qA += v * v;
            v = acc[mb][nb][2] + bb0 + resB.x; acc[mb][nb][2] = v; sB += v; qB += v * v;
            v = acc[mb][nb][3] + bb1 + resB.y; acc[mb][nb][3] = v; sB += v; qB += v * v;
        }
        sA += __shfl_xor_sync(0xffffffffu, sA, 1); qA += __shfl_xor_sync(0xffffffffu, qA, 1);
        sA += __shfl_xor_sync(0xffffffffu, sA, 2); qA += __shfl_xor_sync(0xffffffffu, qA, 2);
        sB += __shfl_xor_sync(0xffffffffu, sB, 1); qB += __shfl_xor_sync(0xffffffffu, qB, 1);
        sB += __shfl_xor_sync(0xffffffffu, sB, 2); qB += __shfl_xor_sync(0xffffffffu, qB, 2);
        if ((lane & 3) == 0) {
            int rlA = mb * 16 + (lane >> 2);
            red[rlA * 8 + w] = make_float2(sA, qA);
            red[(rlA + 8) * 8 + w] = make_float2(sB, qB);
        }
    }
    __syncthreads();

    const float* gam_s = (const float*)(smem + GL_GAM);
    const float* bet_s = (const float*)(smem + GL_BET);
    const int b = bm >> 10;
    int fn = 0;
    if (mode == 2) fn = fnum[b];

#pragma unroll
    for (int mb = 0; mb < 4; mb++) {
#pragma unroll
        for (int hrow = 0; hrow < 2; hrow++) {
            int rl = mb * 16 + hrow * 8 + (lane >> 2);
            int row = bm + rl;
            float su = 0.f, sq = 0.f;
#pragma unroll
            for (int w2 = 0; w2 < 8; w2++) {
                float2 r2 = red[rl * 8 + w2];
                su += r2.x; sq += r2.y;
            }
            float mu = su * (1.0f / Dn);
            float var = sq * (1.0f / Dn) - mu * mu;
            float rs = rsqrtf(var + 1e-5f);

            if (mode == 1) {
#pragma unroll
                for (int nb = 0; nb < 4; nb++) {
                    int cc = w * 32 + nb * 8 + ((lane & 3) << 1);
                    float y0 = (acc[mb][nb][2 * hrow]     - mu) * rs * gam_s[cc]     + bet_s[cc];
                    float y1 = (acc[mb][nb][2 * hrow + 1] - mu) * rs * gam_s[cc + 1] + bet_s[cc + 1];
                    size_t a = (size_t)row * Dn + cc;
                    *(float2*)(Xout + a) = make_float2(y0, y1);
                    *(uint32_t*)(Xh + a) = pack2(y0, y1);
                }
            } else {
                int j = row & 1023;
                if (j < fn) {
                    int idx = il[row];
                    float* op = out + ((size_t)b * NN + idx) * Dn;
#pragma unroll
                    for (int nb = 0; nb < 4; nb++) {
                        int cc = w * 32 + nb * 8 + ((lane & 3) << 1);
                        float y0 = (acc[mb][nb][2 * hrow]     - mu) * rs * gam_s[cc]     + bet_s[cc];
                        float y1 = (acc[mb][nb][2 * hrow + 1] - mu) * rs * gam_s[cc + 1] + bet_s[cc + 1];
                        *(float2*)(op + cc) = make_float2(y0, y1);
                    }
                }
            }
        }
    }
}

// ====================== tensor-core flash attention ========================
// 256 threads, 8 warps x 16 q-rows, 64-key chunks, no-rescale softmax;
// exp interleaved with PV mma per 16-key group.
#define AT_QH 0
#define AT_K  10240             // + buf*5120 : Kh
#define AT_V  20480             // + buf*4608 : Vh
#define AT_SMEM 29696

__global__ __launch_bounds__(256, 2) void attn_tc(
    const __nv_bfloat16* __restrict__ Qh,
    const __nv_bfloat16* __restrict__ Kh, const __nv_bfloat16* __restrict__ Vh,
    __nv_bfloat16* __restrict__ Oh)
{
    extern __shared__ __align__(16) char smem[];
    const uint32_t sb = smem_u32(smem);

    const int tid  = threadIdx.x;
    const int lane = tid & 31;
    const int warp = tid >> 5;
    const int bh   = blockIdx.x;
    const int q0   = blockIdx.y << 7;

    {
        const char* gqh = (const char*)(Qh + ((size_t)bh * 1024 + q0) * 32);
        int row = tid >> 1, seg = tid & 1;
#pragma unroll
        for (int i = 0; i < 2; i++) {
            int s2 = seg * 2 + i;
            size_t go = (size_t)row * 64 + s2 * 16;
            uint32_t so = (uint32_t)row * 80 + s2 * 16;
            CP16(sb + AT_QH + so, gqh + go);
        }
    }

    auto issueKV = [&](int c, int buf) {
        const int kc = c << 6;
        const uint32_t sk = sb + AT_K + buf * 5120;
        const uint32_t sv = sb + AT_V + buf * 4608;
        {
            const char* gkh = (const char*)(Kh + ((size_t)bh * 1024 + kc) * 32);
            int row = tid >> 2, seg = tid & 3;
            size_t go = (size_t)row * 64 + seg * 16;
            uint32_t so = (uint32_t)row * 80 + seg * 16;
            CP16(sk + so, gkh + go);
        }
        {
            const char* gvh = (const char*)(Vh + (size_t)bh * 32 * 1024 + kc);
            int d = tid >> 3, seg = tid & 7;
            size_t go = (size_t)d * 2048 + seg * 16;
            uint32_t so = (uint32_t)d * 144 + seg * 16;
            CP16(sv + so, gvh + go);
        }
        CP_COMMIT();
    };

    issueKV(0, 0);

    float o[4][4];
    float l[2];
#pragma unroll
    for (int b = 0; b < 4; b++)
#pragma unroll
        for (int q = 0; q < 4; q++) o[b][q] = 0.0f;
    l[0] = l[1] = 0.0f;

    uint32_t qfh[2][4];

    const int a_r = lane & 15;
    const int a_c = (lane >> 4) << 3;
    const int b_rr = (lane & 7) + ((lane >> 4) << 3);
    const int b_cc = ((lane >> 3) & 1) << 3;

    for (int c = 0; c < 16; c++) {
        const int buf = c & 1;
        if (c + 1 < 16) { issueKV(c + 1, buf ^ 1); CP_WAIT1(); }
        else            { CP_WAIT0(); }
        __syncthreads();

        if (c == 0) {
#pragma unroll
            for (int kk = 0; kk < 2; kk++) {
                uint32_t ao = (uint32_t)(warp * 16 + a_r) * 80 + (kk * 16 + a_c) * 2;
                LDSM4(qfh[kk], sb + AT_QH + ao);
            }
        }

        const uint32_t sk = sb + AT_K + buf * 5120;
        const uint32_t sv = sb + AT_V + buf * 4608;

        // ---- S = Q K^T (Q already includes BETA) ----
        float s[8][4];
#pragma unroll
        for (int b = 0; b < 8; b++)
#pragma unroll
            for (int q = 0; q < 4; q++) s[b][q] = 0.0f;

#pragma unroll
        for (int g = 0; g < 4; g++) {
            uint32_t kfh[2][4];
#pragma unroll
            for (int kk = 0; kk < 2; kk++) {
                uint32_t bo = (uint32_t)(g * 16 + b_rr) * 80 + (kk * 16 + b_cc) * 2;
                LDSM4(kfh[kk], sk + bo);
            }
#pragma unroll
            for (int nb = 0; nb < 2; nb++) {
                const int nt = g * 2 + nb, sl = nb << 1;
#pragma unroll
                for (int kk = 0; kk < 2; kk++)
                    MMA_BF16(s[nt], qfh[kk], kfh[kk][sl], kfh[kk][sl + 1]);
            }
        }

        // ---- per 16-key group: exp + l + pack + PV mma (interleaved) ----
#pragma unroll
        for (int kt = 0; kt < 4; kt++) {
            uint32_t vfh[2][4];
#pragma unroll
            for (int g = 0; g < 2; g++) {
                uint32_t bo = (uint32_t)(g * 16 + b_rr) * 144 + (kt * 16 + b_cc) * 2;
                LDSM4(vfh[g], sv + bo);
            }
            const int t0 = kt * 2, t1 = kt * 2 + 1;
            float p00 = ex2(fminf(s[t0][0], 60.0f));
            float p01 = ex2(fminf(s[t0][1], 60.0f));
            float p02 = ex2(fminf(s[t0][2], 60.0f));
            float p03 = ex2(fminf(s[t0][3], 60.0f));
            float p10 = ex2(fminf(s[t1][0], 60.0f));
            float p11 = ex2(fminf(s[t1][1], 60.0f));
            float p12 = ex2(fminf(s[t1][2], 60.0f));
            float p13 = ex2(fminf(s[t1][3], 60.0f));
            l[0] += p00 + p01 + p10 + p11;
            l[1] += p02 + p03 + p12 + p13;
            uint32_t ph[4];
            ph[0] = pack2(p00, p01);
            ph[1] = pack2(p02, p03);
            ph[2] = pack2(p10, p11);
            ph[3] = pack2(p12, p13);
#pragma unroll
            for (int nb = 0; nb < 4; nb++) {
                const int g = nb >> 1, sl = (nb & 1) << 1;
                MMA_BF16(o[nb], ph, vfh[g][sl], vfh[g][sl + 1]);
            }
        }
        __syncthreads();
    }

    // ---- final l reduce + normalize + store ----
    l[0] += __shfl_xor_sync(0xffffffffu, l[0], 1);
    l[0] += __shfl_xor_sync(0xffffffffu, l[0], 2);
    l[1] += __shfl_xor_sync(0xffffffffu, l[1], 1);
    l[1] += __shfl_xor_sync(0xffffffffu, l[1], 2);

    const int b  = bh >> 3;
    const int hh = bh & 7;
    {
        float i0 = 1.0f / l[0], i1 = 1.0f / l[1];
#pragma unroll
        for (int h = 0; h < 2; h++) {
            int row = b * 1024 + q0 + warp * 16 + h * 8 + (lane >> 2);
            float inv = h ? i1 : i0;
#pragma unroll
            for (int nb = 0; nb < 4; nb++) {
                int d = nb * 8 + ((lane & 3) << 1);
                float v0 = o[nb][2 * h]     * inv;
                float v1 = o[nb][2 * h + 1] * inv;
                size_t a = (size_t)row * Dn + hh * 32 + d;
                *(uint32_t*)(Oh + a) = pack2(v0, v1);
            }
        }
    }
}

// ---------------------------------------------------------------------------
// Gather + MCSP
// ---------------------------------------------------------------------------
__global__ __launch_bounds__(256) void gather_cls_kernel(
    const float* __restrict__ out, const float* __restrict__ qpos,
    const float* __restrict__ fgs, const int* __restrict__ il,
    const float* __restrict__ Wcls, const float* __restrict__ bcls,
    float* __restrict__ tgt,
    __nv_bfloat16* __restrict__ tgh, __nv_bfloat16* __restrict__ qkh)
{
    __shared__ float qs[Dn];
    __shared__ float sc[16];

    int row = blockIdx.x;
    int b   = row >> 10;
    int t   = threadIdx.x;
    int lane = t & 31, w = t >> 5;
    int idx = il[row];
    size_t src = ((size_t)b * NN + idx) * Dn + t;
    float qv = out[src];
    qs[t] = qv;
    __syncthreads();

#pragma unroll
    for (int ci = 0; ci < 2; ci++) {
        int c = w + ci * 8;
        if (c < NCLSn) {
            float sum = 0.0f;
#pragma unroll
            for (int j = 0; j < 8; j++) {
                int e = lane + (j << 5);
                sum += qs[e] * Wcls[e * NCLSn + c];
            }
#pragma unroll
            for (int o = 16; o; o >>= 1) sum += __shfl_down_sync(0xffffffffu, sum, o);
            if (lane == 0) sc[c] = sum + bcls[c];
        }
    }
    __syncthreads();

    float mx = sc[0];
#pragma unroll
    for (int c = 1; c < NCLSn; c++) mx = fmaxf(mx, sc[c]);
    float mc = (1.0f / (1.0f + __expf(-mx))) * fgs[(size_t)b * NN + idx];

    float tv = tgt[(size_t)row * Dn + t] = qv * mc;
    float qk = tv + qpos[src];
    size_t i = (size_t)row * Dn + t;
    tgh[i] = __float2bfloat16(tv);
    qkh[i] = __float2bfloat16(qk);
}

// ---------------------------------------------------------------------------
// Host-side orchestration
// ---------------------------------------------------------------------------
extern "C" void kernel_launch(void* const* d_in, const int* in_sizes, int n_in,
                              void* d_out, int out_size)
{
    int qp_idx = (in_sizes[1] == 8) ? 4 : 1;

    const float* query = (const float*)d_in[0];
    const float* qpos  = (const float*)d_in[qp_idx];
    const float* fgs   = (const float*)d_in[6];
    const int*   fnum  = (const int*)d_in[7];
    const int*   inds  = (const int*)d_in[8];
    const float* Wq = (const float*)d_in[9],  *bq = (const float*)d_in[10];
    const float* Wk = (const float*)d_in[11], *bk = (const float*)d_in[12];
    const float* Wv = (const float*)d_in[13], *bv = (const float*)d_in[14];
    const float* Wo = (const float*)d_in[15], *bo = (const float*)d_in[16];
    const float* g1 = (const float*)d_in[17], *be1 = (const float*)d_in[18];
    const float* W1 = (const float*)d_in[19], *b1 = (const float*)d_in[20];
    const float* W2 = (const float*)d_in[21], *b2 = (const float*)d_in[22];
    const float* g2 = (const float*)d_in[23], *be2 = (const float*)d_in[24];
    const float* Wcls = (const float*)d_in[25], *bcls = (const float*)d_in[26];

    float* out = (float*)d_out;

    unsigned char* base = nullptr;
    cudaGetSymbolAddress((void**)&base, g_mem);
#define FP(off)  ((float*)(base + (off)))
#define BF(off)  ((__nv_bfloat16*)(base + (off)))

    float *tgt = FP(OF_TGT), *Xb = FP(OF_XB);
    __nv_bfloat16 *qkh = BF(OF_QKH);
    __nv_bfloat16 *tgh = BF(OF_TGH);
    __nv_bfloat16 *qh  = BF(OF_QH);
    __nv_bfloat16 *kh  = BF(OF_KH);
    __nv_bfloat16 *vh  = BF(OF_VH);
    __nv_bfloat16 *ath = BF(OF_ATH);
    __nv_bfloat16 *xh  = BF(OF_XH);
    __nv_bfloat16 *hh  = BF(OF_HH);
    __nv_bfloat16 *wqh = BF(OF_WQH);
    __nv_bfloat16 *wkh = BF(OF_WKH);
    __nv_bfloat16 *wvh = BF(OF_WVH);
    __nv_bfloat16 *woh = BF(OF_WOH);
    __nv_bfloat16 *w1h = BF(OF_W1H);
    __nv_bfloat16 *w2h = BF(OF_W2H);

    cudaFuncSetAttribute(gemm2, cudaFuncAttributeMaxDynamicSharedMemorySize, G2_SMEM);
    cudaFuncSetAttribute(gemm_ln, cudaFuncAttributeMaxDynamicSharedMemorySize, GL_SMEM);
    cudaFuncSetAttribute(attn_tc, cudaFuncAttributeMaxDynamicSharedMemorySize, AT_SMEM);

    {
        WprepP wp{};
        wp.src[0] = Wq; wp.dh[0] = wqh;
        wp.src[1] = Wk; wp.dh[1] = wkh;
        wp.src[2] = Wv; wp.dh[2] = wvh;
        wp.src[3] = Wo; wp.dh[3] = woh;
        wp.src[4] = W1; wp.dh[4] = w1h;
        wp.src[5] = W2; wp.dh[5] = w2h;
        wprep_all<<<4608, 256>>>(wp);
    }

    cudaMemcpyAsync(out, query, sizeof(float) * (size_t)Bn * NN * Dn,
                    cudaMemcpyDeviceToDevice);

    for (int l = 0; l < L_LAYERS; l++) {
        const int* il = inds + (size_t)l * ROWS;
        const size_t wd = (size_t)l * Dn * Dn;
        const size_t wf = (size_t)l * Dn * FFNn;

        gather_cls_kernel<<<ROWS, 256>>>(out, qpos, fgs, il, Wcls, bcls,
                                         tgt, tgh, qkh);

        {   // QKV batched -> head layouts (Q pre-scaled by BETA)
            GemmP p{};
            p.Ah[0] = qkh; p.Wh[0] = wqh + wd; p.bias[0] = bq + l * Dn; p.Ch[0] = qh;
            p.Ah[1] = qkh; p.Wh[1] = wkh + wd; p.bias[1] = bk + l * Dn; p.Ch[1] = kh;
            p.Ah[2] = tgh; p.Wh[2] = wvh + wd; p.bias[2] = bv + l * Dn; p.Ch[2] = vh;
            gemm2<<<dim3(2, 32, 3), 256, G2_SMEM>>>(p, Dn, Dn, 3);
        }

        attn_tc<<<dim3(Bn * Hn, Kn / 128), 256, AT_SMEM>>>(qh, kh, vh, ath);

        // O projection + LN1 fused (res = tgt) -> Xb, xh
        gemm_ln<<<dim3(1, ROWS / 64), 256, GL_SMEM>>>(
            ath, woh + wd,
            bo + l * Dn, g1 + l * Dn, be1 + l * Dn, tgt,
            Xb, xh, nullptr, nullptr, nullptr, Dn, 1);

        {   // FFN1 (relu, bf16 out)
            GemmP p{};
            p.Ah[0] = xh; p.Wh[0] = w1h + wf; p.bias[0] = b1 + l * FFNn; p.Ch[0] = hh;
            gemm2<<<dim3(8, 32, 1), 256, G2_SMEM>>>(p, FFNn, Dn, 2);
        }

        // FFN2 + LN2 + ragged scatter fused (res = Xb) -> out
        gemm_ln<<<dim3(1, ROWS / 64), 256, GL_SMEM>>>(
            hh, w2h + wf,
            b2 + l * Dn, g2 + l * Dn, be2 + l * Dn, Xb,
            nullptr, nullptr, out, il, fnum, FFNn, 2);
    }
}

// round 15
// speedup vs baseline: 1.0988x; 1.0988x over previous
#include <cuda_runtime.h>
#include <cuda_bf16.h>
#include <cstdint>

// ---------------------------------------------------------------------------
// Focus-DETR encoder — round 15: round-13 config (reverted tiles) + attn with
// packed bf16x2 ex2 and mma-computed softmax row sums.
// ---------------------------------------------------------------------------

#define L_LAYERS 6
#define Bn 4
#define NN 23890
#define Kn 1024
#define Dn 256
#define Hn 8
#define HDn 32
#define FFNn 1024
#define NCLSn 15

#define ROWS (Bn * Kn)          // 4096
#define RD   (ROWS * Dn)        // 1048576 elements

// ---------------- scratch carving ----------------
constexpr size_t SZ_F  = (size_t)RD * 4;
constexpr size_t SZ_B  = (size_t)RD * 2;
constexpr size_t SZ_H  = (size_t)ROWS * FFNn * 2;
constexpr size_t SZ_WD = (size_t)L_LAYERS * Dn * Dn * 2;
constexpr size_t SZ_W1 = (size_t)L_LAYERS * Dn * FFNn * 2;

constexpr size_t OF_TGT = 0;
constexpr size_t OF_XB  = OF_TGT + SZ_F;
constexpr size_t OF_QKH = OF_XB  + SZ_F;
constexpr size_t OF_TGH = OF_QKH + SZ_B;
constexpr size_t OF_QH  = OF_TGH + SZ_B;
constexpr size_t OF_KH  = OF_QH  + SZ_B;
constexpr size_t OF_VH  = OF_KH  + SZ_B;
constexpr size_t OF_ATH = OF_VH  + SZ_B;
constexpr size_t OF_XH  = OF_ATH + SZ_B;
constexpr size_t OF_HH  = OF_XH  + SZ_B;
constexpr size_t OF_WQH = OF_HH  + SZ_H;
constexpr size_t OF_WKH = OF_WQH + SZ_WD;
constexpr size_t OF_WVH = OF_WKH + SZ_WD;
constexpr size_t OF_WOH = OF_WVH + SZ_WD;
constexpr size_t OF_W1H = OF_WOH + SZ_WD;
constexpr size_t OF_W2H = OF_W1H + SZ_W1;
constexpr size_t G_TOTAL = OF_W2H + SZ_W1;

__device__ __align__(1024) unsigned char g_mem[G_TOTAL];

#define BETA 0.2550165213f      // log2(e)/sqrt(32), folded into Q

// ============================ PTX helpers ==================================

__device__ __forceinline__ uint32_t smem_u32(const void* p) {
    uint32_t a;
    asm("{ .reg .u64 t; cvta.to.shared.u64 t, %1; cvt.u32.u64 %0, t; }"
        : "=r"(a) : "l"(p));
    return a;
}

#define CP16(sa, ga)                                                            \
    asm volatile("cp.async.ca.shared.global [%0], [%1], 16;"                    \
                 :: "r"(sa), "l"(__cvta_generic_to_global(ga)))
#define CP_COMMIT() asm volatile("cp.async.commit_group;" ::: "memory")
#define CP_WAIT0()  asm volatile("cp.async.wait_group 0;" ::: "memory")
#define CP_WAIT1()  asm volatile("cp.async.wait_group 1;" ::: "memory")

#define LDSM4(r, addr)                                                          \
    asm volatile("ldmatrix.sync.aligned.m8n8.x4.shared.b16 {%0,%1,%2,%3}, [%4];"\
        : "=r"((r)[0]), "=r"((r)[1]), "=r"((r)[2]), "=r"((r)[3]) : "r"(addr))

#define MMA_BF16(d, a, b0, b1)                                                  \
    asm volatile("mma.sync.aligned.m16n8k16.row.col.f32.bf16.bf16.f32 "         \
        "{%0,%1,%2,%3}, {%4,%5,%6,%7}, {%8,%9}, {%0,%1,%2,%3};"                 \
        : "+f"((d)[0]), "+f"((d)[1]), "+f"((d)[2]), "+f"((d)[3])                \
        : "r"((a)[0]), "r"((a)[1]), "r"((a)[2]), "r"((a)[3]), "r"(b0), "r"(b1))

__device__ __forceinline__ uint32_t bf2_u32(__nv_bfloat16 a, __nv_bfloat16 b) {
    union { __nv_bfloat162 v; uint32_t u; } cvt;
    cvt.v = __halves2bfloat162(a, b);
    return cvt.u;
}

__device__ __forceinline__ uint32_t pack2(float v0, float v1) {
    return bf2_u32(__float2bfloat16(v0), __float2bfloat16(v1));
}

__device__ __forceinline__ uint32_t ex2_b2(uint32_t x) {
    uint32_t r;
    asm("ex2.approx.ftz.bf16x2 %0, %1;" : "=r"(r) : "r"(x));
    return r;
}

// ================== weight prep: all weights (hi only) =====================
struct WprepP {
    const float* src[6];
    __nv_bfloat16* dh[6];
};

__global__ __launch_bounds__(256) void wprep_all(WprepP p)
{
    __shared__ float tile[32][33];
    int bid = blockIdx.x;
    int g, layer, kt, nt, Kd, N;
    if (bid < 1536) {
        g = bid / 384; int r = bid % 384;
        layer = r >> 6; int t = r & 63;
        kt = t >> 3; nt = t & 7; Kd = 256; N = 256;
    } else if (bid < 3072) {
        g = 4; int r = bid - 1536;
        layer = r >> 8; int t = r & 255;
        kt = t >> 5; nt = t & 31; Kd = 256; N = 1024;
    } else {
        g = 5; int r = bid - 3072;
        layer = r >> 8; int t = r & 255;
        kt = t >> 3; nt = t & 7; Kd = 1024; N = 256;
    }
    const int k0 = kt << 5, n0 = nt << 5;
    const int tx = threadIdx.x & 31, ty = threadIdx.x >> 5;

    const float* Wp = p.src[g] + (size_t)layer * Kd * N;
#pragma unroll
    for (int r = ty; r < 32; r += 8)
        tile[r][tx] = Wp[(size_t)(k0 + r) * N + n0 + tx];
    __syncthreads();

    __nv_bfloat16* Hp = p.dh[g] + ((size_t)layer * N + n0) * Kd + k0;
#pragma unroll
    for (int r = ty; r < 32; r += 8)
        Hp[(size_t)r * Kd + tx] = __float2bfloat16(tile[tx][r]);
}

// ===================== bf16 GEMM (round-13: 128 thr, 64x128) ===============
struct GemmP {
    const __nv_bfloat16 *Ah[3], *Wh[3];
    const float* bias[3];
    __nv_bfloat16 *Ch[3];
};

#define G2_AH 0
#define G2_BH 5120
#define G2_BUF 15360
#define G2_SMEM (2 * G2_BUF)

__global__ __launch_bounds__(128) void gemm2(GemmP p, int Ncols, int Kd, int mode)
{
    extern __shared__ __align__(16) char smem[];
    const uint32_t sb = smem_u32(smem);

    const int z    = blockIdx.z;
    const __nv_bfloat16* Ah = p.Ah[z];
    const __nv_bfloat16* Wh = p.Wh[z];

    const int tid  = threadIdx.x;
    const int lane = tid & 31;
    const int wn   = tid >> 5;
    const int bm   = blockIdx.y << 6;
    const int bn   = blockIdx.x << 7;

    float acc[4][4][4];
#pragma unroll
    for (int i = 0; i < 4; i++)
#pragma unroll
        for (int j = 0; j < 4; j++)
#pragma unroll
            for (int q = 0; q < 4; q++) acc[i][j][q] = 0.0f;

    const int a_r = lane & 15;
    const int a_c = (lane >> 4) << 3;
    const int b_r = wn * 32 + (lane & 7) + ((lane >> 4) << 3);
    const int b_c = ((lane >> 3) & 1) << 3;

    const int nc = Kd >> 5;

    auto issue = [&](int c, int buf) {
        const uint32_t sa = sb + buf * G2_BUF;
        const size_t kb = (size_t)(c << 5) * 2;
#pragma unroll
        for (int i = 0; i < 2; i++) {
            int s = tid + (i << 7);
            int row = s >> 2, seg = s & 3;
            size_t go = ((size_t)(bm + row) * Kd) * 2 + kb + seg * 16;
            uint32_t so = sa + row * 80 + seg * 16;
            CP16(so + G2_AH, (const char*)Ah + go);
        }
#pragma unroll
        for (int i = 0; i < 4; i++) {
            int s = tid + (i << 7);
            int row = s >> 2, seg = s & 3;
            size_t go = ((size_t)(bn + row) * Kd) * 2 + kb + seg * 16;
            uint32_t so = sa + row * 80 + seg * 16;
            CP16(so + G2_BH, (const char*)Wh + go);
        }
        CP_COMMIT();
    };

    issue(0, 0);

    for (int c = 0; c < nc; c++) {
        const int buf = c & 1;
        if (c + 1 < nc) { issue(c + 1, buf ^ 1); CP_WAIT1(); }
        else           { CP_WAIT0(); }
        __syncthreads();

        const uint32_t sa = sb + buf * G2_BUF;
#pragma unroll
        for (int ks = 0; ks < 2; ks++) {
            uint32_t ah[4][4];
#pragma unroll
            for (int mb = 0; mb < 4; mb++) {
                uint32_t ao = sa + (uint32_t)(a_r + mb * 16) * 80 + (ks * 16 + a_c) * 2;
                LDSM4(ah[mb], ao + G2_AH);
            }
            uint32_t bh[2][4];
#pragma unroll
            for (int np = 0; np < 2; np++) {
                uint32_t bo = sa + (uint32_t)(b_r + np * 16) * 80 + (ks * 16 + b_c) * 2;
                LDSM4(bh[np], bo + G2_BH);
            }
#pragma unroll
            for (int mb = 0; mb < 4; mb++)
#pragma unroll
                for (int nb = 0; nb < 4; nb++) {
                    const int np = nb >> 1, sl = (nb & 1) << 1;
                    MMA_BF16(acc[mb][nb], ah[mb], bh[np][sl], bh[np][sl + 1]);
                }
        }
        __syncthreads();
    }

    const float* bias = p.bias[z];
    const int r0 = bm + (lane >> 2);
    const int c0 = bn + wn * 32 + ((lane & 3) << 1);

    if (mode == 2) {   // FFN1: relu + bf16 out
        __nv_bfloat16* Ch = p.Ch[z];
#pragma unroll
        for (int mb = 0; mb < 4; mb++)
#pragma unroll
            for (int nb = 0; nb < 4; nb++) {
                int rr = r0 + mb * 16, cc = c0 + nb * 8;
                float bb0 = bias[cc], bb1 = bias[cc + 1];
#pragma unroll
                for (int hrow = 0; hrow < 2; hrow++) {
                    int r = rr + hrow * 8;
                    float v0 = fmaxf(acc[mb][nb][2 * hrow]     + bb0, 0.0f);
                    float v1 = fmaxf(acc[mb][nb][2 * hrow + 1] + bb1, 0.0f);
                    *(uint32_t*)(Ch + (size_t)r * Ncols + cc) = pack2(v0, v1);
                }
            }
    } else {           // mode 3: attention QKV layout (Q pre-scaled by BETA)
        __nv_bfloat16* Ch = p.Ch[z];
        const float qscale = (z == 0) ? BETA : 1.0f;
#pragma unroll
        for (int mb = 0; mb < 4; mb++)
#pragma unroll
            for (int nb = 0; nb < 4; nb++) {
                int rr = r0 + mb * 16, cc = c0 + nb * 8;
                float bb0 = bias[cc], bb1 = bias[cc + 1];
                int bh = ((rr >> 10) << 3) + (cc >> 5);
                int d  = cc & 31;
#pragma unroll
                for (int hrow = 0; hrow < 2; hrow++) {
                    int r = rr + hrow * 8;
                    int q = r & 1023;
                    float v0 = (acc[mb][nb][2 * hrow]     + bb0) * qscale;
                    float v1 = (acc[mb][nb][2 * hrow + 1] + bb1) * qscale;
                    if (z < 2) {
                        size_t a = ((size_t)bh * 1024 + q) * 32 + d;
                        *(uint32_t*)(Ch + a) = pack2(v0, v1);
                    } else {
                        size_t a = ((size_t)bh * 32 + d) * 1024 + q;
                        Ch[a] = __float2bfloat16(v0);
                        Ch[a + 1024] = __float2bfloat16(v1);
                    }
                }
            }
    }
}

// ================= GEMM + LayerNorm fused (round-13: 32-row tiles) =========
#define GL_AH 0
#define GL_BH 2560
#define GL_BUF 23040
#define GL_RED   46080
#define GL_BIAS  48128
#define GL_GAM   49152
#define GL_BET   50176
#define GL_SMEM  51200

__global__ __launch_bounds__(256) void gemm_ln(
    const __nv_bfloat16* __restrict__ Ah,
    const __nv_bfloat16* __restrict__ Wh,
    const float* __restrict__ bias, const float* __restrict__ gam,
    const float* __restrict__ bet, const float* __restrict__ res,
    float* __restrict__ Xout, __nv_bfloat16* __restrict__ Xh,
    float* __restrict__ out, const int* __restrict__ il,
    const int* __restrict__ fnum,
    int Kd, int mode)
{
    extern __shared__ __align__(16) char smem[];
    const uint32_t sb = smem_u32(smem);

    const int tid  = threadIdx.x;
    const int lane = tid & 31;
    const int w    = tid >> 5;
    const int bm   = blockIdx.y << 5;

    ((float*)(smem + GL_BIAS))[tid] = bias[tid];
    ((float*)(smem + GL_GAM))[tid]  = gam[tid];
    ((float*)(smem + GL_BET))[tid]  = bet[tid];

    float acc[2][4][4];
#pragma unroll
    for (int i = 0; i < 2; i++)
#pragma unroll
        for (int j = 0; j < 4; j++)
#pragma unroll
            for (int q = 0; q < 4; q++) acc[i][j][q] = 0.0f;

    const int a_r = lane & 15;
    const int a_c = (lane >> 4) << 3;
    const int b_rr = (lane & 7) + ((lane >> 4) << 3);
    const int b_cc = ((lane >> 3) & 1) << 3;

    const int nc = Kd >> 5;

    auto issue = [&](int c, int buf) {
        const uint32_t sa = sb + buf * GL_BUF;
        const size_t kb = (size_t)(c << 5) * 2;
        if (tid < 128) {
            int row = tid >> 2, seg = tid & 3;
            size_t go = ((size_t)(bm + row) * Kd) * 2 + kb + seg * 16;
            uint32_t so = sa + row * 80 + seg * 16;
            CP16(so + GL_AH, (const char*)Ah + go);
        }
#pragma unroll
        for (int i = 0; i < 4; i++) {
            int s = tid + (i << 8);
            int row = s >> 2, seg = s & 3;
            size_t go = ((size_t)row * Kd) * 2 + kb + seg * 16;
            uint32_t so = sa + row * 80 + seg * 16;
            CP16(so + GL_BH, (const char*)Wh + go);
        }
        CP_COMMIT();
    };

    issue(0, 0);

    for (int c = 0; c < nc; c++) {
        const int buf = c & 1;
        if (c + 1 < nc) { issue(c + 1, buf ^ 1); CP_WAIT1(); }
        else           { CP_WAIT0(); }
        __syncthreads();

        const uint32_t sa = sb + buf * GL_BUF;
#pragma unroll
        for (int ks = 0; ks < 2; ks++) {
            uint32_t ah[2][4];
#pragma unroll
            for (int mb = 0; mb < 2; mb++) {
                uint32_t ao = sa + (uint32_t)(mb * 16 + a_r) * 80 + (ks * 16 + a_c) * 2;
                LDSM4(ah[mb], ao + GL_AH);
            }
            uint32_t bh[2][4];
#pragma unroll
            for (int np = 0; np < 2; np++) {
                uint32_t bo = sa + (uint32_t)(w * 32 + np * 16 + b_rr) * 80
                            + (ks * 16 + b_cc) * 2;
                LDSM4(bh[np], bo + GL_BH);
            }
#pragma unroll
            for (int mb = 0; mb < 2; mb++)
#pragma unroll
                for (int nb = 0; nb < 4; nb++) {
                    const int np = nb >> 1, sl = (nb & 1) << 1;
                    MMA_BF16(acc[mb][nb], ah[mb], bh[np][sl], bh[np][sl + 1]);
                }
        }
        __syncthreads();
    }

    const float* bias_s = (const float*)(smem + GL_BIAS);
    float2* red = (float2*)(smem + GL_RED);

#pragma unroll
    for (int mb = 0; mb < 2; mb++) {
        float sA = 0.f, qA = 0.f, sB = 0.f, qB = 0.f;
#pragma unroll
        for (int nb = 0; nb < 4; nb++) {
            int cc = w * 32 + nb * 8 + ((lane & 3) << 1);
            int rA = bm + mb * 16 + (lane >> 2);
            int rB = rA + 8;
            float2 resA = *(const float2*)(res + (size_t)rA * Dn + cc);
            float2 resB = *(const float2*)(res + (size_t)rB * Dn + cc);
            float bb0 = bias_s[cc], bb1 = bias_s[cc + 1];
            float v;
            v = acc[mb][nb][0] + bb0 + resA.x; acc[mb][nb][0] = v; sA += v; qA += v * v;
            v = acc[mb][nb][1] + bb1 + resA.y; acc[mb][nb][1] = v; sA += v; qA += v * v;
            v = acc[mb][nb][2] + bb0 + resB.x; acc[mb][nb][2] = v; sB += v; qB += v * v;
            v = acc[mb][nb][3] + bb1 + resB.y; acc[mb][nb][3] = v; sB += v; qB += v * v;
        }
        sA += __shfl_xor_sync(0xffffffffu, sA, 1); qA += __shfl_xor_sync(0xffffffffu, qA, 1);
        sA += __shfl_xor_sync(0xffffffffu, sA, 2); qA += __shfl_xor_sync(0xffffffffu, qA, 2);
        sB += __shfl_xor_sync(0xffffffffu, sB, 1); qB += __shfl_xor_sync(0xffffffffu, qB, 1);
        sB += __shfl_xor_sync(0xffffffffu, sB, 2); qB += __shfl_xor_sync(0xffffffffu, qB, 2);
        if ((lane & 3) == 0) {
            int rlA = mb * 16 + (lane >> 2);
            red[rlA * 8 + w] = make_float2(sA, qA);
            red[(rlA + 8) * 8 + w] = make_float2(sB, qB);
        }
    }
    __syncthreads();

    const float* gam_s = (const float*)(smem + GL_GAM);
    const float* bet_s = (const float*)(smem + GL_BET);
    const int b = bm >> 10;
    int fn = 0;
    if (mode == 2) fn = fnum[b];

#pragma unroll
    for (int mb = 0; mb < 2; mb++) {
#pragma unroll
        for (int hrow = 0; hrow < 2; hrow++) {
            int rl = mb * 16 + hrow * 8 + (lane >> 2);
            int row = bm + rl;
            float su = 0.f, sq = 0.f;
#pragma unroll
            for (int w2 = 0; w2 < 8; w2++) {
                float2 r2 = red[rl * 8 + w2];
                su += r2.x; sq += r2.y;
            }
            float mu = su * (1.0f / Dn);
            float var = sq * (1.0f / Dn) - mu * mu;
            float rs = rsqrtf(var + 1e-5f);

            if (mode == 1) {
#pragma unroll
                for (int nb = 0; nb < 4; nb++) {
                    int cc = w * 32 + nb * 8 + ((lane & 3) << 1);
                    float y0 = (acc[mb][nb][2 * hrow]     - mu) * rs * gam_s[cc]     + bet_s[cc];
                    float y1 = (acc[mb][nb][2 * hrow + 1] - mu) * rs * gam_s[cc + 1] + bet_s[cc + 1];
                    size_t a = (size_t)row * Dn + cc;
                    *(float2*)(Xout + a) = make_float2(y0, y1);
                    *(uint32_t*)(Xh + a) = pack2(y0, y1);
                }
            } else {
                int j = row & 1023;
                if (j < fn) {
                    int idx = il[row];
                    float* op = out + ((size_t)b * NN + idx) * Dn;
#pragma unroll
                    for (int nb = 0; nb < 4; nb++) {
                        int cc = w * 32 + nb * 8 + ((lane & 3) << 1);
                        float y0 = (acc[mb][nb][2 * hrow]     - mu) * rs * gam_s[cc]     + bet_s[cc];
                        float y1 = (acc[mb][nb][2 * hrow + 1] - mu) * rs * gam_s[cc + 1] + bet_s[cc + 1];
                        *(float2*)(op + cc) = make_float2(y0, y1);
                    }
                }
            }
        }
    }
}

// ====================== tensor-core flash attention ========================
// 256 threads, 8 warps x 16 q-rows, 64-key chunks, no-rescale softmax.
// P computed via packed bf16x2 ex2; softmax sums via mma with ones-B.
#define AT_QH 0
#define AT_K  10240             // + buf*5120 : Kh
#define AT_V  20480             // + buf*4608 : Vh
#define AT_SMEM 29696

__global__ __launch_bounds__(256, 2) void attn_tc(
    const __nv_bfloat16* __restrict__ Qh,
    const __nv_bfloat16* __restrict__ Kh, const __nv_bfloat16* __restrict__ Vh,
    __nv_bfloat16* __restrict__ Oh)
{
    extern __shared__ __align__(16) char smem[];
    const uint32_t sb = smem_u32(smem);

    const int tid  = threadIdx.x;
    const int lane = tid & 31;
    const int warp = tid >> 5;
    const int bh   = blockIdx.x;
    const int q0   = blockIdx.y << 7;

    {
        const char* gqh = (const char*)(Qh + ((size_t)bh * 1024 + q0) * 32);
        int row = tid >> 1, seg = tid & 1;
#pragma unroll
        for (int i = 0; i < 2; i++) {
            int s2 = seg * 2 + i;
            size_t go = (size_t)row * 64 + s2 * 16;
            uint32_t so = (uint32_t)row * 80 + s2 * 16;
            CP16(sb + AT_QH + so, gqh + go);
        }
    }

    auto issueKV = [&](int c, int buf) {
        const int kc = c << 6;
        const uint32_t sk = sb + AT_K + buf * 5120;
        const uint32_t sv = sb + AT_V + buf * 4608;
        {
            const char* gkh = (const char*)(Kh + ((size_t)bh * 1024 + kc) * 32);
            int row = tid >> 2, seg = tid & 3;
            size_t go = (size_t)row * 64 + seg * 16;
            uint32_t so = (uint32_t)row * 80 + seg * 16;
            CP16(sk + so, gkh + go);
        }
        {
            const char* gvh = (const char*)(Vh + (size_t)bh * 32 * 1024 + kc);
            int d = tid >> 3, seg = tid & 7;
            size_t go = (size_t)d * 2048 + seg * 16;
            uint32_t so = (uint32_t)d * 144 + seg * 16;
            CP16(sv + so, gvh + go);
        }
        CP_COMMIT();
    };

    issueKV(0, 0);

    float o[4][4];
    float lacc[4];
#pragma unroll
    for (int b = 0; b < 4; b++)
#pragma unroll
        for (int q = 0; q < 4; q++) o[b][q] = 0.0f;
#pragma unroll
    for (int q = 0; q < 4; q++) lacc[q] = 0.0f;

    uint32_t qfh[2][4];
    const uint32_t ONES = 0x3F803F80u;   // bf16 {1.0, 1.0}

    const int a_r = lane & 15;
    const int a_c = (lane >> 4) << 3;
    const int b_rr = (lane & 7) + ((lane >> 4) << 3);
    const int b_cc = ((lane >> 3) & 1) << 3;

    for (int c = 0; c < 16; c++) {
        const int buf = c & 1;
        if (c + 1 < 16) { issueKV(c + 1, buf ^ 1); CP_WAIT1(); }
        else            { CP_WAIT0(); }
        __syncthreads();

        if (c == 0) {
#pragma unroll
            for (int kk = 0; kk < 2; kk++) {
                uint32_t ao = (uint32_t)(warp * 16 + a_r) * 80 + (kk * 16 + a_c) * 2;
                LDSM4(qfh[kk], sb + AT_QH + ao);
            }
        }

        const uint32_t sk = sb + AT_K + buf * 5120;
        const uint32_t sv = sb + AT_V + buf * 4608;

        // ---- S = Q K^T (Q already includes BETA) ----
        float s[8][4];
#pragma unroll
        for (int b = 0; b < 8; b++)
#pragma unroll
            for (int q = 0; q < 4; q++) s[b][q] = 0.0f;

#pragma unroll
        for (int g = 0; g < 4; g++) {
            uint32_t kfh[2][4];
#pragma unroll
            for (int kk = 0; kk < 2; kk++) {
                uint32_t bo = (uint32_t)(g * 16 + b_rr) * 80 + (kk * 16 + b_cc) * 2;
                LDSM4(kfh[kk], sk + bo);
            }
#pragma unroll
            for (int nb = 0; nb < 2; nb++) {
                const int nt = g * 2 + nb, sl = nb << 1;
#pragma unroll
                for (int kk = 0; kk < 2; kk++)
                    MMA_BF16(s[nt], qfh[kk], kfh[kk][sl], kfh[kk][sl + 1]);
            }
        }

        // ---- pack clamped s to bf16x2, then packed ex2 ----
        uint32_t pp[4][4];
#pragma unroll
        for (int kt = 0; kt < 4; kt++) {
            const int t0 = kt * 2, t1 = t0 + 1;
            pp[kt][0] = pack2(fminf(s[t0][0], 60.0f), fminf(s[t0][1], 60.0f));
            pp[kt][1] = pack2(fminf(s[t0][2], 60.0f), fminf(s[t0][3], 60.0f));
            pp[kt][2] = pack2(fminf(s[t1][0], 60.0f), fminf(s[t1][1], 60.0f));
            pp[kt][3] = pack2(fminf(s[t1][2], 60.0f), fminf(s[t1][3], 60.0f));
            pp[kt][0] = ex2_b2(pp[kt][0]);
            pp[kt][1] = ex2_b2(pp[kt][1]);
            pp[kt][2] = ex2_b2(pp[kt][2]);
            pp[kt][3] = ex2_b2(pp[kt][3]);
        }

        // ---- O += P V ; l += P * ones ----
#pragma unroll
        for (int kt = 0; kt < 4; kt++) {
            uint32_t vfh[2][4];
#pragma unroll
            for (int g = 0; g < 2; g++) {
                uint32_t bo = (uint32_t)(g * 16 + b_rr) * 144 + (kt * 16 + b_cc) * 2;
                LDSM4(vfh[g], sv + bo);
            }
#pragma unroll
            for (int nb = 0; nb < 4; nb++) {
                const int g = nb >> 1, sl = (nb & 1) << 1;
                MMA_BF16(o[nb], pp[kt], vfh[g][sl], vfh[g][sl + 1]);
            }
            MMA_BF16(lacc, pp[kt], ONES, ONES);
        }
        __syncthreads();
    }

    // lacc[0] = row sum (h=0), lacc[2] = row sum (h=1); no shuffles needed.
    const int b  = bh >> 3;
    const int hh = bh & 7;
    {
        float i0 = 1.0f / lacc[0], i1 = 1.0f / lacc[2];
#pragma unroll
        for (int h = 0; h < 2; h++) {
            int row = b * 1024 + q0 + warp * 16 + h * 8 + (lane >> 2);
            float inv = h ? i1 : i0;
#pragma unroll
            for (int nb = 0; nb < 4; nb++) {
                int d = nb * 8 + ((lane & 3) << 1);
                float v0 = o[nb][2 * h]     * inv;
                float v1 = o[nb][2 * h + 1] * inv;
                size_t a = (size_t)row * Dn + hh * 32 + d;
                *(uint32_t*)(Oh + a) = pack2(v0, v1);
            }
        }
    }
}

// ---------------------------------------------------------------------------
// Gather + MCSP
// ---------------------------------------------------------------------------
__global__ __launch_bounds__(256) void gather_cls_kernel(
    const float* __restrict__ out, const float* __restrict__ qpos,
    const float* __restrict__ fgs, const int* __restrict__ il,
    const float* __restrict__ Wcls, const float* __restrict__ bcls,
    float* __restrict__ tgt,
    __nv_bfloat16* __restrict__ tgh, __nv_bfloat16* __restrict__ qkh)
{
    __shared__ float qs[Dn];
    __shared__ float sc[16];

    int row = blockIdx.x;
    int b   = row >> 10;
    int t   = threadIdx.x;
    int lane = t & 31, w = t >> 5;
    int idx = il[row];
    size_t src = ((size_t)b * NN + idx) * Dn + t;
    float qv = out[src];
    qs[t] = qv;
    __syncthreads();

#pragma unroll
    for (int ci = 0; ci < 2; ci++) {
        int c = w + ci * 8;
        if (c < NCLSn) {
            float sum = 0.0f;
#pragma unroll
            for (int j = 0; j < 8; j++) {
                int e = lane + (j << 5);
                sum += qs[e] * Wcls[e * NCLSn + c];
            }
#pragma unroll
            for (int o = 16; o; o >>= 1) sum += __shfl_down_sync(0xffffffffu, sum, o);
            if (lane == 0) sc[c] = sum + bcls[c];
        }
    }
    __syncthreads();

    float mx = sc[0];
#pragma unroll
    for (int c = 1; c < NCLSn; c++) mx = fmaxf(mx, sc[c]);
    float mc = (1.0f / (1.0f + __expf(-mx))) * fgs[(size_t)b * NN + idx];

    float tv = tgt[(size_t)row * Dn + t] = qv * mc;
    float qk = tv + qpos[src];
    size_t i = (size_t)row * Dn + t;
    tgh[i] = __float2bfloat16(tv);
    qkh[i] = __float2bfloat16(qk);
}

// ---------------------------------------------------------------------------
// Host-side orchestration
// ---------------------------------------------------------------------------
extern "C" void kernel_launch(void* const* d_in, const int* in_sizes, int n_in,
                              void* d_out, int out_size)
{
    int qp_idx = (in_sizes[1] == 8) ? 4 : 1;

    const float* query = (const float*)d_in[0];
    const float* qpos  = (const float*)d_in[qp_idx];
    const float* fgs   = (const float*)d_in[6];
    const int*   fnum  = (const int*)d_in[7];
    const int*   inds  = (const int*)d_in[8];
    const float* Wq = (const float*)d_in[9],  *bq = (const float*)d_in[10];
    const float* Wk = (const float*)d_in[11], *bk = (const float*)d_in[12];
    const float* Wv = (const float*)d_in[13], *bv = (const float*)d_in[14];
    const float* Wo = (const float*)d_in[15], *bo = (const float*)d_in[16];
    const float* g1 = (const float*)d_in[17], *be1 = (const float*)d_in[18];
    const float* W1 = (const float*)d_in[19], *b1 = (const float*)d_in[20];
    const float* W2 = (const float*)d_in[21], *b2 = (const float*)d_in[22];
    const float* g2 = (const float*)d_in[23], *be2 = (const float*)d_in[24];
    const float* Wcls = (const float*)d_in[25], *bcls = (const float*)d_in[26];

    float* out = (float*)d_out;

    unsigned char* base = nullptr;
    cudaGetSymbolAddress((void**)&base, g_mem);
#define FP(off)  ((float*)(base + (off)))
#define BF(off)  ((__nv_bfloat16*)(base + (off)))

    float *tgt = FP(OF_TGT), *Xb = FP(OF_XB);
    __nv_bfloat16 *qkh = BF(OF_QKH);
    __nv_bfloat16 *tgh = BF(OF_TGH);
    __nv_bfloat16 *qh  = BF(OF_QH);
    __nv_bfloat16 *kh  = BF(OF_KH);
    __nv_bfloat16 *vh  = BF(OF_VH);
    __nv_bfloat16 *ath = BF(OF_ATH);
    __nv_bfloat16 *xh  = BF(OF_XH);
    __nv_bfloat16 *hh  = BF(OF_HH);
    __nv_bfloat16 *wqh = BF(OF_WQH);
    __nv_bfloat16 *wkh = BF(OF_WKH);
    __nv_bfloat16 *wvh = BF(OF_WVH);
    __nv_bfloat16 *woh = BF(OF_WOH);
    __nv_bfloat16 *w1h = BF(OF_W1H);
    __nv_bfloat16 *w2h = BF(OF_W2H);

    cudaFuncSetAttribute(gemm2, cudaFuncAttributeMaxDynamicSharedMemorySize, G2_SMEM);
    cudaFuncSetAttribute(gemm_ln, cudaFuncAttributeMaxDynamicSharedMemorySize, GL_SMEM);
    cudaFuncSetAttribute(attn_tc, cudaFuncAttributeMaxDynamicSharedMemorySize, AT_SMEM);

    {
        WprepP wp{};
        wp.src[0] = Wq; wp.dh[0] = wqh;
        wp.src[1] = Wk; wp.dh[1] = wkh;
        wp.src[2] = Wv; wp.dh[2] = wvh;
        wp.src[3] = Wo; wp.dh[3] = woh;
        wp.src[4] = W1; wp.dh[4] = w1h;
        wp.src[5] = W2; wp.dh[5] = w2h;
        wprep_all<<<4608, 256>>>(wp);
    }

    cudaMemcpyAsync(out, query, sizeof(float) * (size_t)Bn * NN * Dn,
                    cudaMemcpyDeviceToDevice);

    for (int l = 0; l < L_LAYERS; l++) {
        const int* il = inds + (size_t)l * ROWS;
        const size_t wd = (size_t)l * Dn * Dn;
        const size_t wf = (size_t)l * Dn * FFNn;

        gather_cls_kernel<<<ROWS, 256>>>(out, qpos, fgs, il, Wcls, bcls,
                                         tgt, tgh, qkh);

        {   // QKV batched -> head layouts (Q pre-scaled by BETA)
            GemmP p{};
            p.Ah[0] = qkh; p.Wh[0] = wqh + wd; p.bias[0] = bq + l * Dn; p.Ch[0] = qh;
            p.Ah[1] = qkh; p.Wh[1] = wkh + wd; p.bias[1] = bk + l * Dn; p.Ch[1] = kh;
            p.Ah[2] = tgh; p.Wh[2] = wvh + wd; p.bias[2] = bv + l * Dn; p.Ch[2] = vh;
            gemm2<<<dim3(2, 64, 3), 128, G2_SMEM>>>(p, Dn, Dn, 3);
        }

        attn_tc<<<dim3(Bn * Hn, Kn / 128), 256, AT_SMEM>>>(qh, kh, vh, ath);

        // O projection + LN1 fused (res = tgt) -> Xb, xh
        gemm_ln<<<dim3(1, ROWS / 32), 256, GL_SMEM>>>(
            ath, woh + wd,
            bo + l * Dn, g1 + l * Dn, be1 + l * Dn, tgt,
            Xb, xh, nullptr, nullptr, nullptr, Dn, 1);

        {   // FFN1 (relu, bf16 out)
            GemmP p{};
            p.Ah[0] = xh; p.Wh[0] = w1h + wf; p.bias[0] = b1 + l * FFNn; p.Ch[0] = hh;
            gemm2<<<dim3(8, 64, 1), 128, G2_SMEM>>>(p, FFNn, Dn, 2);
        }

        // FFN2 + LN2 + ragged scatter fused (res = Xb) -> out
        gemm_ln<<<dim3(1, ROWS / 32), 256, GL_SMEM>>>(
            hh, w2h + wf,
            b2 + l * Dn, g2 + l * Dn, be2 + l * Dn, Xb,
            nullptr, nullptr, out, il, fnum, FFNn, 2);
    }
}

// round 16
// speedup vs baseline: 1.1132x; 1.0130x over previous
#include <cuda_runtime.h>
#include <cuda_bf16.h>
#include <cstdint>

// ---------------------------------------------------------------------------
// Focus-DETR encoder — round 16: round-13 numerics/config exactly, with
// attn_tc forced to 3 CTAs/SM (launch_bounds(256,3)) for latency coverage.
// ---------------------------------------------------------------------------

#define L_LAYERS 6
#define Bn 4
#define NN 23890
#define Kn 1024
#define Dn 256
#define Hn 8
#define HDn 32
#define FFNn 1024
#define NCLSn 15

#define ROWS (Bn * Kn)          // 4096
#define RD   (ROWS * Dn)        // 1048576 elements

// ---------------- scratch carving ----------------
constexpr size_t SZ_F  = (size_t)RD * 4;
constexpr size_t SZ_B  = (size_t)RD * 2;
constexpr size_t SZ_H  = (size_t)ROWS * FFNn * 2;
constexpr size_t SZ_WD = (size_t)L_LAYERS * Dn * Dn * 2;
constexpr size_t SZ_W1 = (size_t)L_LAYERS * Dn * FFNn * 2;

constexpr size_t OF_TGT = 0;
constexpr size_t OF_XB  = OF_TGT + SZ_F;
constexpr size_t OF_QKH = OF_XB  + SZ_F;
constexpr size_t OF_TGH = OF_QKH + SZ_B;
constexpr size_t OF_QH  = OF_TGH + SZ_B;
constexpr size_t OF_KH  = OF_QH  + SZ_B;
constexpr size_t OF_VH  = OF_KH  + SZ_B;
constexpr size_t OF_ATH = OF_VH  + SZ_B;
constexpr size_t OF_XH  = OF_ATH + SZ_B;
constexpr size_t OF_HH  = OF_XH  + SZ_B;
constexpr size_t OF_WQH = OF_HH  + SZ_H;
constexpr size_t OF_WKH = OF_WQH + SZ_WD;
constexpr size_t OF_WVH = OF_WKH + SZ_WD;
constexpr size_t OF_WOH = OF_WVH + SZ_WD;
constexpr size_t OF_W1H = OF_WOH + SZ_WD;
constexpr size_t OF_W2H = OF_W1H + SZ_W1;
constexpr size_t G_TOTAL = OF_W2H + SZ_W1;

__device__ __align__(1024) unsigned char g_mem[G_TOTAL];

#define BETA 0.2550165213f      // log2(e)/sqrt(32), folded into Q

// ============================ PTX helpers ==================================

__device__ __forceinline__ uint32_t smem_u32(const void* p) {
    uint32_t a;
    asm("{ .reg .u64 t; cvta.to.shared.u64 t, %1; cvt.u32.u64 %0, t; }"
        : "=r"(a) : "l"(p));
    return a;
}

#define CP16(sa, ga)                                                            \
    asm volatile("cp.async.ca.shared.global [%0], [%1], 16;"                    \
                 :: "r"(sa), "l"(__cvta_generic_to_global(ga)))
#define CP_COMMIT() asm volatile("cp.async.commit_group;" ::: "memory")
#define CP_WAIT0()  asm volatile("cp.async.wait_group 0;" ::: "memory")
#define CP_WAIT1()  asm volatile("cp.async.wait_group 1;" ::: "memory")

#define LDSM4(r, addr)                                                          \
    asm volatile("ldmatrix.sync.aligned.m8n8.x4.shared.b16 {%0,%1,%2,%3}, [%4];"\
        : "=r"((r)[0]), "=r"((r)[1]), "=r"((r)[2]), "=r"((r)[3]) : "r"(addr))

#define MMA_BF16(d, a, b0, b1)                                                  \
    asm volatile("mma.sync.aligned.m16n8k16.row.col.f32.bf16.bf16.f32 "         \
        "{%0,%1,%2,%3}, {%4,%5,%6,%7}, {%8,%9}, {%0,%1,%2,%3};"                 \
        : "+f"((d)[0]), "+f"((d)[1]), "+f"((d)[2]), "+f"((d)[3])                \
        : "r"((a)[0]), "r"((a)[1]), "r"((a)[2]), "r"((a)[3]), "r"(b0), "r"(b1))

__device__ __forceinline__ uint32_t bf2_u32(__nv_bfloat16 a, __nv_bfloat16 b) {
    union { __nv_bfloat162 v; uint32_t u; } cvt;
    cvt.v = __halves2bfloat162(a, b);
    return cvt.u;
}

__device__ __forceinline__ uint32_t pack2(float v0, float v1) {
    return bf2_u32(__float2bfloat16(v0), __float2bfloat16(v1));
}

__device__ __forceinline__ float ex2(float x) {
    float r;
    asm("ex2.approx.ftz.f32 %0, %1;" : "=f"(r) : "f"(x));
    return r;
}

// ================== weight prep: all weights (hi only) =====================
struct WprepP {
    const float* src[6];
    __nv_bfloat16* dh[6];
};

__global__ __launch_bounds__(256) void wprep_all(WprepP p)
{
    __shared__ float tile[32][33];
    int bid = blockIdx.x;
    int g, layer, kt, nt, Kd, N;
    if (bid < 1536) {
        g = bid / 384; int r = bid % 384;
        layer = r >> 6; int t = r & 63;
        kt = t >> 3; nt = t & 7; Kd = 256; N = 256;
    } else if (bid < 3072) {
        g = 4; int r = bid - 1536;
        layer = r >> 8; int t = r & 255;
        kt = t >> 5; nt = t & 31; Kd = 256; N = 1024;
    } else {
        g = 5; int r = bid - 3072;
        layer = r >> 8; int t = r & 255;
        kt = t >> 3; nt = t & 7; Kd = 1024; N = 256;
    }
    const int k0 = kt << 5, n0 = nt << 5;
    const int tx = threadIdx.x & 31, ty = threadIdx.x >> 5;

    const float* Wp = p.src[g] + (size_t)layer * Kd * N;
#pragma unroll
    for (int r = ty; r < 32; r += 8)
        tile[r][tx] = Wp[(size_t)(k0 + r) * N + n0 + tx];
    __syncthreads();

    __nv_bfloat16* Hp = p.dh[g] + ((size_t)layer * N + n0) * Kd + k0;
#pragma unroll
    for (int r = ty; r < 32; r += 8)
        Hp[(size_t)r * Kd + tx] = __float2bfloat16(tile[tx][r]);
}

// ===================== bf16 GEMM (single-term mma) =========================
struct GemmP {
    const __nv_bfloat16 *Ah[3], *Wh[3];
    const float* bias[3];
    __nv_bfloat16 *Ch[3];
};

#define G2_AH 0
#define G2_BH 5120
#define G2_BUF 15360
#define G2_SMEM (2 * G2_BUF)

__global__ __launch_bounds__(128) void gemm2(GemmP p, int Ncols, int Kd, int mode)
{
    extern __shared__ __align__(16) char smem[];
    const uint32_t sb = smem_u32(smem);

    const int z    = blockIdx.z;
    const __nv_bfloat16* Ah = p.Ah[z];
    const __nv_bfloat16* Wh = p.Wh[z];

    const int tid  = threadIdx.x;
    const int lane = tid & 31;
    const int wn   = tid >> 5;
    const int bm   = blockIdx.y << 6;
    const int bn   = blockIdx.x << 7;

    float acc[4][4][4];
#pragma unroll
    for (int i = 0; i < 4; i++)
#pragma unroll
        for (int j = 0; j < 4; j++)
#pragma unroll
            for (int q = 0; q < 4; q++) acc[i][j][q] = 0.0f;

    const int a_r = lane & 15;
    const int a_c = (lane >> 4) << 3;
    const int b_r = wn * 32 + (lane & 7) + ((lane >> 4) << 3);
    const int b_c = ((lane >> 3) & 1) << 3;

    const int nc = Kd >> 5;

    auto issue = [&](int c, int buf) {
        const uint32_t sa = sb + buf * G2_BUF;
        const size_t kb = (size_t)(c << 5) * 2;
#pragma unroll
        for (int i = 0; i < 2; i++) {
            int s = tid + (i << 7);
            int row = s >> 2, seg = s & 3;
            size_t go = ((size_t)(bm + row) * Kd) * 2 + kb + seg * 16;
            uint32_t so = sa + row * 80 + seg * 16;
            CP16(so + G2_AH, (const char*)Ah + go);
        }
#pragma unroll
        for (int i = 0; i < 4; i++) {
            int s = tid + (i << 7);
            int row = s >> 2, seg = s & 3;
            size_t go = ((size_t)(bn + row) * Kd) * 2 + kb + seg * 16;
            uint32_t so = sa + row * 80 + seg * 16;
            CP16(so + G2_BH, (const char*)Wh + go);
        }
        CP_COMMIT();
    };

    issue(0, 0);

    for (int c = 0; c < nc; c++) {
        const int buf = c & 1;
        if (c + 1 < nc) { issue(c + 1, buf ^ 1); CP_WAIT1(); }
        else           { CP_WAIT0(); }
        __syncthreads();

        const uint32_t sa = sb + buf * G2_BUF;
#pragma unroll
        for (int ks = 0; ks < 2; ks++) {
            uint32_t ah[4][4];
#pragma unroll
            for (int mb = 0; mb < 4; mb++) {
                uint32_t ao = sa + (uint32_t)(a_r + mb * 16) * 80 + (ks * 16 + a_c) * 2;
                LDSM4(ah[mb], ao + G2_AH);
            }
            uint32_t bh[2][4];
#pragma unroll
            for (int np = 0; np < 2; np++) {
                uint32_t bo = sa + (uint32_t)(b_r + np * 16) * 80 + (ks * 16 + b_c) * 2;
                LDSM4(bh[np], bo + G2_BH);
            }
#pragma unroll
            for (int mb = 0; mb < 4; mb++)
#pragma unroll
                for (int nb = 0; nb < 4; nb++) {
                    const int np = nb >> 1, sl = (nb & 1) << 1;
                    MMA_BF16(acc[mb][nb], ah[mb], bh[np][sl], bh[np][sl + 1]);
                }
        }
        __syncthreads();
    }

    const float* bias = p.bias[z];
    const int r0 = bm + (lane >> 2);
    const int c0 = bn + wn * 32 + ((lane & 3) << 1);

    if (mode == 2) {   // FFN1: relu + bf16 out
        __nv_bfloat16* Ch = p.Ch[z];
#pragma unroll
        for (int mb = 0; mb < 4; mb++)
#pragma unroll
            for (int nb = 0; nb < 4; nb++) {
                int rr = r0 + mb * 16, cc = c0 + nb * 8;
                float bb0 = bias[cc], bb1 = bias[cc + 1];
#pragma unroll
                for (int hrow = 0; hrow < 2; hrow++) {
                    int r = rr + hrow * 8;
                    float v0 = fmaxf(acc[mb][nb][2 * hrow]     + bb0, 0.0f);
                    float v1 = fmaxf(acc[mb][nb][2 * hrow + 1] + bb1, 0.0f);
                    *(uint32_t*)(Ch + (size_t)r * Ncols + cc) = pack2(v0, v1);
                }
            }
    } else {           // mode 3: attention QKV layout (Q pre-scaled by BETA)
        __nv_bfloat16* Ch = p.Ch[z];
        const float qscale = (z == 0) ? BETA : 1.0f;
#pragma unroll
        for (int mb = 0; mb < 4; mb++)
#pragma unroll
            for (int nb = 0; nb < 4; nb++) {
                int rr = r0 + mb * 16, cc = c0 + nb * 8;
                float bb0 = bias[cc], bb1 = bias[cc + 1];
                int bh = ((rr >> 10) << 3) + (cc >> 5);
                int d  = cc & 31;
#pragma unroll
                for (int hrow = 0; hrow < 2; hrow++) {
                    int r = rr + hrow * 8;
                    int q = r & 1023;
                    float v0 = (acc[mb][nb][2 * hrow]     + bb0) * qscale;
                    float v1 = (acc[mb][nb][2 * hrow + 1] + bb1) * qscale;
                    if (z < 2) {
                        size_t a = ((size_t)bh * 1024 + q) * 32 + d;
                        *(uint32_t*)(Ch + a) = pack2(v0, v1);
                    } else {
                        size_t a = ((size_t)bh * 32 + d) * 1024 + q;
                        Ch[a] = __float2bfloat16(v0);
                        Ch[a + 1024] = __float2bfloat16(v1);
                    }
                }
            }
    }
}

// ================= GEMM + LayerNorm fused (32-row tiles) ===================
#define GL_AH 0
#define GL_BH 2560
#define GL_BUF 23040
#define GL_RED   46080
#define GL_BIAS  48128
#define GL_GAM   49152
#define GL_BET   50176
#define GL_SMEM  51200

__global__ __launch_bounds__(256) void gemm_ln(
    const __nv_bfloat16* __restrict__ Ah,
    const __nv_bfloat16* __restrict__ Wh,
    const float* __restrict__ bias, const float* __restrict__ gam,
    const float* __restrict__ bet, const float* __restrict__ res,
    float* __restrict__ Xout, __nv_bfloat16* __restrict__ Xh,
    float* __restrict__ out, const int* __restrict__ il,
    const int* __restrict__ fnum,
    int Kd, int mode)
{
    extern __shared__ __align__(16) char smem[];
    const uint32_t sb = smem_u32(smem);

    const int tid  = threadIdx.x;
    const int lane = tid & 31;
    const int w    = tid >> 5;
    const int bm   = blockIdx.y << 5;

    ((float*)(smem + GL_BIAS))[tid] = bias[tid];
    ((float*)(smem + GL_GAM))[tid]  = gam[tid];
    ((float*)(smem + GL_BET))[tid]  = bet[tid];

    float acc[2][4][4];
#pragma unroll
    for (int i = 0; i < 2; i++)
#pragma unroll
        for (int j = 0; j < 4; j++)
#pragma unroll
            for (int q = 0; q < 4; q++) acc[i][j][q] = 0.0f;

    const int a_r = lane & 15;
    const int a_c = (lane >> 4) << 3;
    const int b_rr = (lane & 7) + ((lane >> 4) << 3);
    const int b_cc = ((lane >> 3) & 1) << 3;

    const int nc = Kd >> 5;

    auto issue = [&](int c, int buf) {
        const uint32_t sa = sb + buf * GL_BUF;
        const size_t kb = (size_t)(c << 5) * 2;
        if (tid < 128) {
            int row = tid >> 2, seg = tid & 3;
            size_t go = ((size_t)(bm + row) * Kd) * 2 + kb + seg * 16;
            uint32_t so = sa + row * 80 + seg * 16;
            CP16(so + GL_AH, (const char*)Ah + go);
        }
#pragma unroll
        for (int i = 0; i < 4; i++) {
            int s = tid + (i << 8);
            int row = s >> 2, seg = s & 3;
            size_t go = ((size_t)row * Kd) * 2 + kb + seg * 16;
            uint32_t so = sa + row * 80 + seg * 16;
            CP16(so + GL_BH, (const char*)Wh + go);
        }
        CP_COMMIT();
    };

    issue(0, 0);

    for (int c = 0; c < nc; c++) {
        const int buf = c & 1;
        if (c + 1 < nc) { issue(c + 1, buf ^ 1); CP_WAIT1(); }
        else           { CP_WAIT0(); }
        __syncthreads();

        const uint32_t sa = sb + buf * GL_BUF;
#pragma unroll
        for (int ks = 0; ks < 2; ks++) {
            uint32_t ah[2][4];
#pragma unroll
            for (int mb = 0; mb < 2; mb++) {
                uint32_t ao = sa + (uint32_t)(mb * 16 + a_r) * 80 + (ks * 16 + a_c) * 2;
                LDSM4(ah[mb], ao + GL_AH);
            }
            uint32_t bh[2][4];
#pragma unroll
            for (int np = 0; np < 2; np++) {
                uint32_t bo = sa + (uint32_t)(w * 32 + np * 16 + b_rr) * 80
                            + (ks * 16 + b_cc) * 2;
                LDSM4(bh[np], bo + GL_BH);
            }
#pragma unroll
            for (int mb = 0; mb < 2; mb++)
#pragma unroll
                for (int nb = 0; nb < 4; nb++) {
                    const int np = nb >> 1, sl = (nb & 1) << 1;
                    MMA_BF16(acc[mb][nb], ah[mb], bh[np][sl], bh[np][sl + 1]);
                }
        }
        __syncthreads();
    }

    const float* bias_s = (const float*)(smem + GL_BIAS);
    float2* red = (float2*)(smem + GL_RED);

#pragma unroll
    for (int mb = 0; mb < 2; mb++) {
        float sA = 0.f, qA = 0.f, sB = 0.f, qB = 0.f;
#pragma unroll
        for (int nb = 0; nb < 4; nb++) {
            int cc = w * 32 + nb * 8 + ((lane & 3) << 1);
            int rA = bm + mb * 16 + (lane >> 2);
            int rB = rA + 8;
            float2 resA = *(const float2*)(res + (size_t)rA * Dn + cc);
            float2 resB = *(const float2*)(res + (size_t)rB * Dn + cc);
            float bb0 = bias_s[cc], bb1 = bias_s[cc + 1];
            float v;
            v = acc[mb][nb][0] + bb0 + resA.x; acc[mb][nb][0] = v; sA += v; qA += v * v;
            v = acc[mb][nb][1] + bb1 + resA.y; acc[mb][nb][1] = v; sA += v; qA += v * v;
            v = acc[mb][nb][2] + bb0 + resB.x; acc[mb][nb][2] = v; sB += v; qB += v * v;
            v = acc[mb][nb][3] + bb1 + resB.y; acc[mb][nb][3] = v; sB += v; qB += v * v;
        }
        sA += __shfl_xor_sync(0xffffffffu, sA, 1); qA += __shfl_xor_sync(0xffffffffu, qA, 1);
        sA += __shfl_xor_sync(0xffffffffu, sA, 2); qA += __shfl_xor_sync(0xffffffffu, qA, 2);
        sB += __shfl_xor_sync(0xffffffffu, sB, 1); qB += __shfl_xor_sync(0xffffffffu, qB, 1);
        sB += __shfl_xor_sync(0xffffffffu, sB, 2); qB += __shfl_xor_sync(0xffffffffu, qB, 2);
        if ((lane & 3) == 0) {
            int rlA = mb * 16 + (lane >> 2);
            red[rlA * 8 + w] = make_float2(sA, qA);
            red[(rlA + 8) * 8 + w] = make_float2(sB, qB);
        }
    }
    __syncthreads();

    const float* gam_s = (const float*)(smem + GL_GAM);
    const float* bet_s = (const float*)(smem + GL_BET);
    const int b = bm >> 10;
    int fn = 0;
    if (mode == 2) fn = fnum[b];

#pragma unroll
    for (int mb = 0; mb < 2; mb++) {
#pragma unroll
        for (int hrow = 0; hrow < 2; hrow++) {
            int rl = mb * 16 + hrow * 8 + (lane >> 2);
            int row = bm + rl;
            float su = 0.f, sq = 0.f;
#pragma unroll
            for (int w2 = 0; w2 < 8; w2++) {
                float2 r2 = red[rl * 8 + w2];
                su += r2.x; sq += r2.y;
            }
            float mu = su * (1.0f / Dn);
            float var = sq * (1.0f / Dn) - mu * mu;
            float rs = rsqrtf(var + 1e-5f);

            if (mode == 1) {
#pragma unroll
                for (int nb = 0; nb < 4; nb++) {
                    int cc = w * 32 + nb * 8 + ((lane & 3) << 1);
                    float y0 = (acc[mb][nb][2 * hrow]     - mu) * rs * gam_s[cc]     + bet_s[cc];
                    float y1 = (acc[mb][nb][2 * hrow + 1] - mu) * rs * gam_s[cc + 1] + bet_s[cc + 1];
                    size_t a = (size_t)row * Dn + cc;
                    *(float2*)(Xout + a) = make_float2(y0, y1);
                    *(uint32_t*)(Xh + a) = pack2(y0, y1);
                }
            } else {
                int j = row & 1023;
                if (j < fn) {
                    int idx = il[row];
                    float* op = out + ((size_t)b * NN + idx) * Dn;
#pragma unroll
                    for (int nb = 0; nb < 4; nb++) {
                        int cc = w * 32 + nb * 8 + ((lane & 3) << 1);
                        float y0 = (acc[mb][nb][2 * hrow]     - mu) * rs * gam_s[cc]     + bet_s[cc];
                        float y1 = (acc[mb][nb][2 * hrow + 1] - mu) * rs * gam_s[cc + 1] + bet_s[cc + 1];
                        *(float2*)(op + cc) = make_float2(y0, y1);
                    }
                }
            }
        }
    }
}

// ====================== tensor-core flash attention ========================
// 256 threads, 8 warps x 16 q-rows, 64-key chunks, no-rescale softmax
// (round-13 body), 3 CTAs/SM forced for latency coverage.
#define AT_QH 0
#define AT_K  10240             // + buf*5120 : Kh
#define AT_V  20480             // + buf*4608 : Vh
#define AT_SMEM 29696

__global__ __launch_bounds__(256, 3) void attn_tc(
    const __nv_bfloat16* __restrict__ Qh,
    const __nv_bfloat16* __restrict__ Kh, const __nv_bfloat16* __restrict__ Vh,
    __nv_bfloat16* __restrict__ Oh)
{
    extern __shared__ __align__(16) char smem[];
    const uint32_t sb = smem_u32(smem);

    const int tid  = threadIdx.x;
    const int lane = tid & 31;
    const int warp = tid >> 5;
    const int bh   = blockIdx.x;
    const int q0   = blockIdx.y << 7;

    {
        const char* gqh = (const char*)(Qh + ((size_t)bh * 1024 + q0) * 32);
        int row = tid >> 1, seg = tid & 1;
#pragma unroll
        for (int i = 0; i < 2; i++) {
            int s2 = seg * 2 + i;
            size_t go = (size_t)row * 64 + s2 * 16;
            uint32_t so = (uint32_t)row * 80 + s2 * 16;
            CP16(sb + AT_QH + so, gqh + go);
        }
    }

    auto issueKV = [&](int c, int buf) {
        const int kc = c << 6;
        const uint32_t sk = sb + AT_K + buf * 5120;
        const uint32_t sv = sb + AT_V + buf * 4608;
        {
            const char* gkh = (const char*)(Kh + ((size_t)bh * 1024 + kc) * 32);
            int row = tid >> 2, seg = tid & 3;
            size_t go = (size_t)row * 64 + seg * 16;
            uint32_t so = (uint32_t)row * 80 + seg * 16;
            CP16(sk + so, gkh + go);
        }
        {
            const char* gvh = (const char*)(Vh + (size_t)bh * 32 * 1024 + kc);
            int d = tid >> 3, seg = tid & 7;
            size_t go = (size_t)d * 2048 + seg * 16;
            uint32_t so = (uint32_t)d * 144 + seg * 16;
            CP16(sv + so, gvh + go);
        }
        CP_COMMIT();
    };

    issueKV(0, 0);

    float o[4][4];
    float l[2];
#pragma unroll
    for (int b = 0; b < 4; b++)
#pragma unroll
        for (int q = 0; q < 4; q++) o[b][q] = 0.0f;
    l[0] = l[1] = 0.0f;

    uint32_t qfh[2][4];

    const int a_r = lane & 15;
    const int a_c = (lane >> 4) << 3;
    const int b_rr = (lane & 7) + ((lane >> 4) << 3);
    const int b_cc = ((lane >> 3) & 1) << 3;

    for (int c = 0; c < 16; c++) {
        const int buf = c & 1;
        if (c + 1 < 16) { issueKV(c + 1, buf ^ 1); CP_WAIT1(); }
        else            { CP_WAIT0(); }
        __syncthreads();

        if (c == 0) {
#pragma unroll
            for (int kk = 0; kk < 2; kk++) {
                uint32_t ao = (uint32_t)(warp * 16 + a_r) * 80 + (kk * 16 + a_c) * 2;
                LDSM4(qfh[kk], sb + AT_QH + ao);
            }
        }

        const uint32_t sk = sb + AT_K + buf * 5120;
        const uint32_t sv = sb + AT_V + buf * 4608;

        // ---- S = Q K^T (Q already includes BETA) ----
        float s[8][4];
#pragma unroll
        for (int b = 0; b < 8; b++)
#pragma unroll
            for (int q = 0; q < 4; q++) s[b][q] = 0.0f;

#pragma unroll
        for (int g = 0; g < 4; g++) {
            uint32_t kfh[2][4];
#pragma unroll
            for (int kk = 0; kk < 2; kk++) {
                uint32_t bo = (uint32_t)(g * 16 + b_rr) * 80 + (kk * 16 + b_cc) * 2;
                LDSM4(kfh[kk], sk + bo);
            }
#pragma unroll
            for (int nb = 0; nb < 2; nb++) {
                const int nt = g * 2 + nb, sl = nb << 1;
#pragma unroll
                for (int kk = 0; kk < 2; kk++)
                    MMA_BF16(s[nt], qfh[kk], kfh[kk][sl], kfh[kk][sl + 1]);
            }
        }

        // ---- P = 2^min(s,60) ; accumulate l partials ----
#pragma unroll
        for (int nt = 0; nt < 8; nt++) {
            s[nt][0] = ex2(fminf(s[nt][0], 60.0f));
            s[nt][1] = ex2(fminf(s[nt][1], 60.0f));
            s[nt][2] = ex2(fminf(s[nt][2], 60.0f));
            s[nt][3] = ex2(fminf(s[nt][3], 60.0f));
            l[0] += s[nt][0] + s[nt][1];
            l[1] += s[nt][2] + s[nt][3];
        }

        // ---- O += P V ----
#pragma unroll
        for (int kt = 0; kt < 4; kt++) {
            uint32_t vfh[2][4];
#pragma unroll
            for (int g = 0; g < 2; g++) {
                uint32_t bo = (uint32_t)(g * 16 + b_rr) * 144 + (kt * 16 + b_cc) * 2;
                LDSM4(vfh[g], sv + bo);
            }
            const int t0 = kt * 2, t1 = kt * 2 + 1;
            uint32_t ph[4];
            ph[0] = pack2(s[t0][0], s[t0][1]);
            ph[1] = pack2(s[t0][2], s[t0][3]);
            ph[2] = pack2(s[t1][0], s[t1][1]);
            ph[3] = pack2(s[t1][2], s[t1][3]);
#pragma unroll
            for (int nb = 0; nb < 4; nb++) {
                const int g = nb >> 1, sl = (nb & 1) << 1;
                MMA_BF16(o[nb], ph, vfh[g][sl], vfh[g][sl + 1]);
            }
        }
        __syncthreads();
    }

    // ---- final l reduce + normalize + store ----
    l[0] += __shfl_xor_sync(0xffffffffu, l[0], 1);
    l[0] += __shfl_xor_sync(0xffffffffu, l[0], 2);
    l[1] += __shfl_xor_sync(0xffffffffu, l[1], 1);
    l[1] += __shfl_xor_sync(0xffffffffu, l[1], 2);

    const int b  = bh >> 3;
    const int hh = bh & 7;
    {
        float i0 = 1.0f / l[0], i1 = 1.0f / l[1];
#pragma unroll
        for (int h = 0; h < 2; h++) {
            int row = b * 1024 + q0 + warp * 16 + h * 8 + (lane >> 2);
            float inv = h ? i1 : i0;
#pragma unroll
            for (int nb = 0; nb < 4; nb++) {
                int d = nb * 8 + ((lane & 3) << 1);
                float v0 = o[nb][2 * h]     * inv;
                float v1 = o[nb][2 * h + 1] * inv;
                size_t a = (size_t)row * Dn + hh * 32 + d;
                *(uint32_t*)(Oh + a) = pack2(v0, v1);
            }
        }
    }
}

// ---------------------------------------------------------------------------
// Gather + MCSP
// ---------------------------------------------------------------------------
__global__ __launch_bounds__(256) void gather_cls_kernel(
    const float* __restrict__ out, const float* __restrict__ qpos,
    const float* __restrict__ fgs, const int* __restrict__ il,
    const float* __restrict__ Wcls, const float* __restrict__ bcls,
    float* __restrict__ tgt,
    __nv_bfloat16* __restrict__ tgh, __nv_bfloat16* __restrict__ qkh)
{
    __shared__ float qs[Dn];
    __shared__ float sc[16];

    int row = blockIdx.x;
    int b   = row >> 10;
    int t   = threadIdx.x;
    int lane = t & 31, w = t >> 5;
    int idx = il[row];
    size_t src = ((size_t)b * NN + idx) * Dn + t;
    float qv = out[src];
    qs[t] = qv;
    __syncthreads();

#pragma unroll
    for (int ci = 0; ci < 2; ci++) {
        int c = w + ci * 8;
        if (c < NCLSn) {
            float sum = 0.0f;
#pragma unroll
            for (int j = 0; j < 8; j++) {
                int e = lane + (j << 5);
                sum += qs[e] * Wcls[e * NCLSn + c];
            }
#pragma unroll
            for (int o = 16; o; o >>= 1) sum += __shfl_down_sync(0xffffffffu, sum, o);
            if (lane == 0) sc[c] = sum + bcls[c];
        }
    }
    __syncthreads();

    float mx = sc[0];
#pragma unroll
    for (int c = 1; c < NCLSn; c++) mx = fmaxf(mx, sc[c]);
    float mc = (1.0f / (1.0f + __expf(-mx))) * fgs[(size_t)b * NN + idx];

    float tv = tgt[(size_t)row * Dn + t] = qv * mc;
    float qk = tv + qpos[src];
    size_t i = (size_t)row * Dn + t;
    tgh[i] = __float2bfloat16(tv);
    qkh[i] = __float2bfloat16(qk);
}

// ---------------------------------------------------------------------------
// Host-side orchestration
// ---------------------------------------------------------------------------
extern "C" void kernel_launch(void* const* d_in, const int* in_sizes, int n_in,
                              void* d_out, int out_size)
{
    int qp_idx = (in_sizes[1] == 8) ? 4 : 1;

    const float* query = (const float*)d_in[0];
    const float* qpos  = (const float*)d_in[qp_idx];
    const float* fgs   = (const float*)d_in[6];
    const int*   fnum  = (const int*)d_in[7];
    const int*   inds  = (const int*)d_in[8];
    const float* Wq = (const float*)d_in[9],  *bq = (const float*)d_in[10];
    const float* Wk = (const float*)d_in[11], *bk = (const float*)d_in[12];
    const float* Wv = (const float*)d_in[13], *bv = (const float*)d_in[14];
    const float* Wo = (const float*)d_in[15], *bo = (const float*)d_in[16];
    const float* g1 = (const float*)d_in[17], *be1 = (const float*)d_in[18];
    const float* W1 = (const float*)d_in[19], *b1 = (const float*)d_in[20];
    const float* W2 = (const float*)d_in[21], *b2 = (const float*)d_in[22];
    const float* g2 = (const float*)d_in[23], *be2 = (const float*)d_in[24];
    const float* Wcls = (const float*)d_in[25], *bcls = (const float*)d_in[26];

    float* out = (float*)d_out;

    unsigned char* base = nullptr;
    cudaGetSymbolAddress((void**)&base, g_mem);
#define FP(off)  ((float*)(base + (off)))
#define BF(off)  ((__nv_bfloat16*)(base + (off)))

    float *tgt = FP(OF_TGT), *Xb = FP(OF_XB);
    __nv_bfloat16 *qkh = BF(OF_QKH);
    __nv_bfloat16 *tgh = BF(OF_TGH);
    __nv_bfloat16 *qh  = BF(OF_QH);
    __nv_bfloat16 *kh  = BF(OF_KH);
    __nv_bfloat16 *vh  = BF(OF_VH);
    __nv_bfloat16 *ath = BF(OF_ATH);
    __nv_bfloat16 *xh  = BF(OF_XH);
    __nv_bfloat16 *hh  = BF(OF_HH);
    __nv_bfloat16 *wqh = BF(OF_WQH);
    __nv_bfloat16 *wkh = BF(OF_WKH);
    __nv_bfloat16 *wvh = BF(OF_WVH);
    __nv_bfloat16 *woh = BF(OF_WOH);
    __nv_bfloat16 *w1h = BF(OF_W1H);
    __nv_bfloat16 *w2h = BF(OF_W2H);

    cudaFuncSetAttribute(gemm2, cudaFuncAttributeMaxDynamicSharedMemorySize, G2_SMEM);
    cudaFuncSetAttribute(gemm_ln, cudaFuncAttributeMaxDynamicSharedMemorySize, GL_SMEM);
    cudaFuncSetAttribute(attn_tc, cudaFuncAttributeMaxDynamicSharedMemorySize, AT_SMEM);

    {
        WprepP wp{};
        wp.src[0] = Wq; wp.dh[0] = wqh;
        wp.src[1] = Wk; wp.dh[1] = wkh;
        wp.src[2] = Wv; wp.dh[2] = wvh;
        wp.src[3] = Wo; wp.dh[3] = woh;
        wp.src[4] = W1; wp.dh[4] = w1h;
        wp.src[5] = W2; wp.dh[5] = w2h;
        wprep_all<<<4608, 256>>>(wp);
    }

    cudaMemcpyAsync(out, query, sizeof(float) * (size_t)Bn * NN * Dn,
                    cudaMemcpyDeviceToDevice);

    for (int l = 0; l < L_LAYERS; l++) {
        const int* il = inds + (size_t)l * ROWS;
        const size_t wd = (size_t)l * Dn * Dn;
        const size_t wf = (size_t)l * Dn * FFNn;

        gather_cls_kernel<<<ROWS, 256>>>(out, qpos, fgs, il, Wcls, bcls,
                                         tgt, tgh, qkh);

        {   // QKV batched -> head layouts (Q pre-scaled by BETA)
            GemmP p{};
            p.Ah[0] = qkh; p.Wh[0] = wqh + wd; p.bias[0] = bq + l * Dn; p.Ch[0] = qh;
            p.Ah[1] = qkh; p.Wh[1] = wkh + wd; p.bias[1] = bk + l * Dn; p.Ch[1] = kh;
            p.Ah[2] = tgh; p.Wh[2] = wvh + wd; p.bias[2] = bv + l * Dn; p.Ch[2] = vh;
            gemm2<<<dim3(2, 64, 3), 128, G2_SMEM>>>(p, Dn, Dn, 3);
        }

        attn_tc<<<dim3(Bn * Hn, Kn / 128), 256, AT_SMEM>>>(qh, kh, vh, ath);

        // O projection + LN1 fused (res = tgt) -> Xb, xh
        gemm_ln<<<dim3(1, ROWS / 32), 256, GL_SMEM>>>(
            ath, woh + wd,
            bo + l * Dn, g1 + l * Dn, be1 + l * Dn, tgt,
            Xb, xh, nullptr, nullptr, nullptr, Dn, 1);

        {   // FFN1 (relu, bf16 out)
            GemmP p{};
            p.Ah[0] = xh; p.Wh[0] = w1h + wf; p.bias[0] = b1 + l * FFNn; p.Ch[0] = hh;
            gemm2<<<dim3(8, 64, 1), 128, G2_SMEM>>>(p, FFNn, Dn, 2);
        }

        // FFN2 + LN2 + ragged scatter fused (res = Xb) -> out
        gemm_ln<<<dim3(1, ROWS / 32), 256, GL_SMEM>>>(
            hh, w2h + wf,
            b2 + l * Dn, g2 + l * Dn, be2 + l * Dn, Xb,
            nullptr, nullptr, out, il, fnum, FFNn, 2);
    }
}